// round 5
// baseline (speedup 1.0000x reference)
#include <cuda_runtime.h>
#include <cstdint>
#include <cstddef>

// ============================================================================
// SNN: 50 timesteps of (GEMM + LIF) x 3 layers on plain-sm_103 tensor path:
// mma.sync.m16n8k32.s8.s8.s32 + ldmatrix + cp.async.
// Weights quantized to 28-bit fixed point, split into 3 balanced int8 digits:
//   v = round(w * 2^28) = d2*65536 + d1*256 + d0,  |di| <= 128
// Binary spikes are int8-exact, so each digit GEMM accumulates EXACTLY in s32
// (|acc| <= 4096*128 = 524288). Epilogue combines digits in fp32 (exact) and
// scales by 2^-28. Per-weight error <= 2^-29; no accumulation-ordering noise.
// ============================================================================

#define TSTEPS 50
#define BATCH  256
#define INDIM  1536
#define H1D    4096
#define H2D    4096
#define OUTD   64
#define KSPLIT 16

// ---------------- persistent scratch (device globals) -----------------------
__device__ __align__(128) int8_t g_spk_in[(size_t)TSTEPS * BATCH * INDIM];
__device__ __align__(128) int8_t g_s1[(size_t)BATCH * H1D];
__device__ __align__(128) int8_t g_s2[(size_t)BATCH * H2D];
__device__ __align__(128) float g_mem1[(size_t)BATCH * H1D];
__device__ __align__(128) float g_mem2[(size_t)BATCH * H2D];
__device__ __align__(128) float g_mem3[(size_t)BATCH * OUTD];
__device__ __align__(128) float g_part[(size_t)KSPLIT * BATCH * OUTD];
// digit arrays: a = d2 (x65536), b = d1 (x256), c = d0 (x1)
__device__ __align__(128) int8_t g_W1a[(size_t)H1D * INDIM];
__device__ __align__(128) int8_t g_W1b[(size_t)H1D * INDIM];
__device__ __align__(128) int8_t g_W1c[(size_t)H1D * INDIM];
__device__ __align__(128) int8_t g_W2a[(size_t)H2D * H1D];
__device__ __align__(128) int8_t g_W2b[(size_t)H2D * H1D];
__device__ __align__(128) int8_t g_W2c[(size_t)H2D * H1D];
__device__ __align__(128) int8_t g_W3a[(size_t)OUTD * H2D];
__device__ __align__(128) int8_t g_W3b[(size_t)OUTD * H2D];
__device__ __align__(128) int8_t g_W3c[(size_t)OUTD * H2D];

#define INVS 3.725290298461914e-09f   // 2^-28

// ------------------------------ asm helpers ---------------------------------
__device__ __forceinline__ uint32_t smem_u32(const void* p) {
    uint32_t a;
    asm("{ .reg .u64 t; cvta.to.shared.u64 t, %1; cvt.u32.u64 %0, t; }"
        : "=r"(a) : "l"(p));
    return a;
}

__device__ __forceinline__ void cp16(uint32_t smem, const void* gmem) {
    asm volatile("cp.async.cg.shared.global [%0], [%1], 16;"
                 :: "r"(smem), "l"(gmem) : "memory");
}
__device__ __forceinline__ void cp_commit() {
    asm volatile("cp.async.commit_group;" ::: "memory");
}
template<int N>
__device__ __forceinline__ void cp_wait() {
    asm volatile("cp.async.wait_group %0;" :: "n"(N) : "memory");
}

__device__ __forceinline__ void ldsm4(uint32_t (&r)[4], uint32_t addr) {
    asm volatile("ldmatrix.sync.aligned.m8n8.x4.shared.b16 {%0,%1,%2,%3}, [%4];"
                 : "=r"(r[0]), "=r"(r[1]), "=r"(r[2]), "=r"(r[3]) : "r"(addr));
}

__device__ __forceinline__ void imma16832(int (&d)[4], const uint32_t (&a)[4],
                                          uint32_t b0, uint32_t b1) {
    asm volatile(
        "mma.sync.aligned.m16n8k32.row.col.s32.s8.s8.s32 "
        "{%0,%1,%2,%3}, {%4,%5,%6,%7}, {%8,%9}, {%0,%1,%2,%3};"
        : "+r"(d[0]), "+r"(d[1]), "+r"(d[2]), "+r"(d[3])
        : "r"(a[0]), "r"(a[1]), "r"(a[2]), "r"(a[3]), "r"(b0), "r"(b1));
}

// ============================================================================
// GEMM (+ LIF epilogue or split-K partial store).
//   D[m,n] = sum_k A[m0+m,k] * (65536*Wa + 256*Wb + Wc)[n0+n,k] * 2^-28
// CTA: M=128 x N=64, 256 threads, warps 4(m) x 2(n), warp tile 32x32.
// 5-stage cp.async ring; stage = A(128x128 s8) + 3x W(64x128 s8) = 40KB.
// K-chunk per stage = 128. For LIF kernels, blockIdx.z==1 blocks instead run
// the previous step's layer-3 split-K reduction + LIF3 + output accumulation.
// ============================================================================
template<bool LIF>
__global__ void __launch_bounds__(256, 1) gemm_lif(
    const int8_t* __restrict__ A, int lda,
    const int8_t* __restrict__ Wa,
    const int8_t* __restrict__ Wb,
    const int8_t* __restrict__ Wc,
    int ldw, int nk,
    const float* __restrict__ bias,
    float* __restrict__ memv,
    int8_t* __restrict__ spk, int ldn,
    float* __restrict__ part,
    const float* __restrict__ r_part,
    const float* __restrict__ r_b3,
    float* __restrict__ r_mem3,
    float* __restrict__ r_out)
{
    constexpr int S = 5;
    constexpr int ABYTES = 128 * 128;          // 16KB: 128 rows x 128 s8
    constexpr int BCOMP  = 64 * 128;           // 8KB per weight digit
    constexpr int STAGE  = ABYTES + 3 * BCOMP; // 40KB

    const int tid = threadIdx.x;

    // ---- fused reduce blocks (previous step's layer-3 epilogue) -------------
    if (LIF && blockIdx.z == 1) {
        const int bid = (int)(blockIdx.y * 2 + blockIdx.x);
        if (bid < (BATCH * OUTD) / 256) {
            const int idx = bid * 256 + tid;
            const int n = idx & (OUTD - 1);
            float s = r_b3[n];
            #pragma unroll
            for (int zz = 0; zz < KSPLIT; ++zz)
                s += r_part[(size_t)zz * BATCH * OUTD + idx];
            const float mo = r_mem3[idx];
            const float mn = 0.9f * mo + s - ((mo > 1.0f) ? 1.0f : 0.0f);
            r_mem3[idx] = mn;
            r_out[idx] += ((mn > 1.0f) ? 1.0f : 0.0f);
        }
        return;
    }

    extern __shared__ char smem[];
    const uint32_t sbase = smem_u32(smem);

    const int lane = tid & 31;
    const int wid  = tid >> 5;
    const int m0   = blockIdx.x * 128;
    const int n0   = blockIdx.y * 64;
    const int z    = blockIdx.z;
    const int kbase = LIF ? 0 : z * nk * 128;

    const int warp_m = (wid >> 1) * 32;  // 0,32,64,96
    const int warp_n = (wid & 1) * 32;   // 0,32

    // ---- stage loader -------------------------------------------------------
    auto load_stage = [&](int L) {
        if (L >= nk) return;
        const uint32_t st = sbase + (uint32_t)(L % S) * STAGE;
        const int k0 = kbase + L * 128;
        // A: 1024 16B-slots, 4 per thread
        #pragma unroll
        for (int i = 0; i < 4; ++i) {
            const int idx  = tid + i * 256;
            const int row  = idx >> 3;
            const int slot = idx & 7;
            const int8_t* g = A + (size_t)(m0 + row) * lda + k0 + slot * 16;
            cp16(st + (uint32_t)row * 128u + (uint32_t)((slot ^ (row & 7)) << 4), g);
        }
        // B: 3 digits x 512 slots, 2 per thread per digit
        #pragma unroll
        for (int c = 0; c < 3; ++c) {
            const int8_t* W = (c == 0) ? Wa : ((c == 1) ? Wb : Wc);
            const uint32_t bb = st + ABYTES + (uint32_t)c * BCOMP;
            #pragma unroll
            for (int i = 0; i < 2; ++i) {
                const int idx  = tid + i * 256;
                const int row  = idx >> 3;
                const int slot = idx & 7;
                const int8_t* g = W + (size_t)(n0 + row) * ldw + k0 + slot * 16;
                cp16(bb + (uint32_t)row * 128u + (uint32_t)((slot ^ (row & 7)) << 4), g);
            }
        }
    };

    // ---- pipeline prologue ---------------------------------------------------
    #pragma unroll
    for (int L = 0; L < S - 1; ++L) { load_stage(L); cp_commit(); }

    int acc[3][2][4][4];   // [digit][mt][nt][e]
    #pragma unroll
    for (int c = 0; c < 3; ++c)
        #pragma unroll
        for (int mt = 0; mt < 2; ++mt)
            #pragma unroll
            for (int nt = 0; nt < 4; ++nt)
                #pragma unroll
                for (int e = 0; e < 4; ++e) acc[c][mt][nt][e] = 0;

    const int a_row = (lane & 7) | (((lane >> 3) & 1) << 3);
    const int a_sel = lane >> 4;
    const int b_row = (lane & 7) | (((lane >> 4) & 1) << 3);
    const int b_sel = (lane >> 3) & 1;

    // ---- main loop ------------------------------------------------------------
    for (int it = 0; it < nk; ++it) {
        cp_wait<S - 2>();
        __syncthreads();
        load_stage(it + S - 1);
        cp_commit();

        const uint32_t st = sbase + (uint32_t)(it % S) * STAGE;

        // A fragments: 2 m-tiles x 4 k32-chunks (32B each = 2 slots)
        uint32_t afr[2][4][4];
        #pragma unroll
        for (int mt = 0; mt < 2; ++mt) {
            #pragma unroll
            for (int kk = 0; kk < 4; ++kk) {
                const int row  = warp_m + mt * 16 + a_row;
                const int slot = kk * 2 + a_sel;
                ldsm4(afr[mt][kk],
                      st + (uint32_t)row * 128u + (uint32_t)((slot ^ (row & 7)) << 4));
            }
        }

        #pragma unroll
        for (int c = 0; c < 3; ++c) {
            const uint32_t bb = st + ABYTES + (uint32_t)c * BCOMP;
            uint32_t bfr[4][2][4];
            #pragma unroll
            for (int kk = 0; kk < 4; ++kk) {
                #pragma unroll
                for (int jn = 0; jn < 2; ++jn) {
                    const int row  = warp_n + jn * 16 + b_row;
                    const int slot = kk * 2 + b_sel;
                    ldsm4(bfr[kk][jn],
                          bb + (uint32_t)row * 128u + (uint32_t)((slot ^ (row & 7)) << 4));
                }
            }
            #pragma unroll
            for (int kk = 0; kk < 4; ++kk)
                #pragma unroll
                for (int mt = 0; mt < 2; ++mt)
                    #pragma unroll
                    for (int nt = 0; nt < 4; ++nt)
                        imma16832(acc[c][mt][nt], afr[mt][kk],
                                  bfr[kk][nt >> 1][(nt & 1) * 2],
                                  bfr[kk][nt >> 1][(nt & 1) * 2 + 1]);
        }
    }

    // ---- epilogue: combine digits exactly in fp32, then LIF / partial store --
    const int col2 = (lane & 3) * 2;
    const int rowg = lane >> 2;
    #pragma unroll
    for (int mt = 0; mt < 2; ++mt) {
        #pragma unroll
        for (int nt = 0; nt < 4; ++nt) {
            const int n = n0 + warp_n + nt * 8 + col2;
            const int mbase = m0 + warp_m + mt * 16 + rowg;
            float cur[4];
            #pragma unroll
            for (int e = 0; e < 4; ++e) {
                cur[e] = fmaf(65536.0f, (float)acc[0][mt][nt][e],
                         fmaf(256.0f,   (float)acc[1][mt][nt][e],
                                        (float)acc[2][mt][nt][e])) * INVS;
            }
            if (LIF) {
                const float2 bv = *(const float2*)(bias + n);
                #pragma unroll
                for (int h = 0; h < 2; ++h) {
                    const int m = mbase + h * 8;
                    const size_t off = (size_t)m * ldn + n;
                    float2 mo = *(float2*)(memv + off);
                    const float c0 = cur[h * 2 + 0] + bv.x;
                    const float c1 = cur[h * 2 + 1] + bv.y;
                    const float mn0 = 0.9f * mo.x + c0 - ((mo.x > 1.0f) ? 1.0f : 0.0f);
                    const float mn1 = 0.9f * mo.y + c1 - ((mo.y > 1.0f) ? 1.0f : 0.0f);
                    float2 mw; mw.x = mn0; mw.y = mn1;
                    *(float2*)(memv + off) = mw;
                    uchar2 sv;
                    sv.x = (mn0 > 1.0f) ? 1 : 0;
                    sv.y = (mn1 > 1.0f) ? 1 : 0;
                    *(uchar2*)(spk + off) = sv;
                }
            } else {
                float* po = part + (size_t)z * BATCH * OUTD;
                #pragma unroll
                for (int h = 0; h < 2; ++h) {
                    const int m = mbase + h * 8;
                    float2 pv; pv.x = cur[h * 2 + 0]; pv.y = cur[h * 2 + 1];
                    *(float2*)(po + (size_t)m * OUTD + n) = pv;
                }
            }
        }
    }
}

// ============================================================================
// Single prep kernel: spike convert + 3 weight digit-splits + state zeroing.
// One launch so profiled launches >= 1 are GEMMs.
// ============================================================================
__device__ __forceinline__ void split_one(const float* __restrict__ W,
                                          int8_t* __restrict__ a,
                                          int8_t* __restrict__ b,
                                          int8_t* __restrict__ c,
                                          int n, int gid, int st) {
    for (int i = gid; i < n; i += st) {
        const int v  = __float2int_rn(W[i] * 268435456.0f);   // 2^28
        const int d0 = ((v + 128) & 255) - 128;
        const int t  = (v - d0) >> 8;
        const int d1 = ((t + 128) & 255) - 128;
        const int d2 = (t - d1) >> 8;
        a[i] = (int8_t)d2; b[i] = (int8_t)d1; c[i] = (int8_t)d0;
    }
}

__global__ void k_prep(const float* __restrict__ x, int8_t* __restrict__ xs, int nx,
                       const float* __restrict__ W1, int8_t* w1a, int8_t* w1b, int8_t* w1c, int n1,
                       const float* __restrict__ W2, int8_t* w2a, int8_t* w2b, int8_t* w2c, int n2,
                       const float* __restrict__ W3, int8_t* w3a, int8_t* w3b, int8_t* w3c, int n3,
                       float* __restrict__ z1, int nz1,
                       float* __restrict__ z2, int nz2,
                       float* __restrict__ z3, int nz3,
                       float* __restrict__ z4, int nz4) {
    const int gid = blockIdx.x * blockDim.x + threadIdx.x;
    const int st  = gridDim.x * blockDim.x;
    for (int i = gid; i < nx; i += st) xs[i] = (int8_t)(x[i] > 0.5f ? 1 : 0);
    split_one(W1, w1a, w1b, w1c, n1, gid, st);
    split_one(W2, w2a, w2b, w2c, n2, gid, st);
    split_one(W3, w3a, w3b, w3c, n3, gid, st);
    for (int i = gid; i < nz1; i += st) z1[i] = 0.0f;
    for (int i = gid; i < nz2; i += st) z2[i] = 0.0f;
    for (int i = gid; i < nz3; i += st) z3[i] = 0.0f;
    for (int i = gid; i < nz4; i += st) z4[i] = 0.0f;
}

__global__ void k_reduce3(const float* __restrict__ part,
                          const float* __restrict__ b3,
                          float* __restrict__ mem3,
                          float* __restrict__ out) {
    const int idx = blockIdx.x * blockDim.x + threadIdx.x;   // 16384 threads exact
    const int n = idx & (OUTD - 1);
    float s = b3[n];
    #pragma unroll
    for (int zz = 0; zz < KSPLIT; ++zz)
        s += part[(size_t)zz * BATCH * OUTD + idx];
    const float mo = mem3[idx];
    const float mn = 0.9f * mo + s - ((mo > 1.0f) ? 1.0f : 0.0f);
    mem3[idx] = mn;
    out[idx] += ((mn > 1.0f) ? 1.0f : 0.0f);
}

// ============================================================================
// Host launcher
// ============================================================================
extern "C" void kernel_launch(void* const* d_in, const int* in_sizes, int n_in,
                              void* d_out, int out_size) {
    (void)in_sizes; (void)n_in; (void)out_size;

    const float* spike_seq = (const float*)d_in[0];
    const float* W1 = (const float*)d_in[1];
    const float* b1 = (const float*)d_in[2];
    const float* W2 = (const float*)d_in[3];
    const float* b2 = (const float*)d_in[4];
    const float* W3 = (const float*)d_in[5];
    const float* b3 = (const float*)d_in[6];
    float* out = (float*)d_out;

    void *p_spk, *p_s1, *p_s2, *p_m1, *p_m2, *p_m3, *p_part;
    void *p_w1a, *p_w1b, *p_w1c, *p_w2a, *p_w2b, *p_w2c, *p_w3a, *p_w3b, *p_w3c;
    cudaGetSymbolAddress(&p_spk, g_spk_in);
    cudaGetSymbolAddress(&p_s1, g_s1);   cudaGetSymbolAddress(&p_s2, g_s2);
    cudaGetSymbolAddress(&p_m1, g_mem1); cudaGetSymbolAddress(&p_m2, g_mem2);
    cudaGetSymbolAddress(&p_m3, g_mem3); cudaGetSymbolAddress(&p_part, g_part);
    cudaGetSymbolAddress(&p_w1a, g_W1a); cudaGetSymbolAddress(&p_w1b, g_W1b);
    cudaGetSymbolAddress(&p_w1c, g_W1c);
    cudaGetSymbolAddress(&p_w2a, g_W2a); cudaGetSymbolAddress(&p_w2b, g_W2b);
    cudaGetSymbolAddress(&p_w2c, g_W2c);
    cudaGetSymbolAddress(&p_w3a, g_W3a); cudaGetSymbolAddress(&p_w3b, g_W3b);
    cudaGetSymbolAddress(&p_w3c, g_W3c);

    int8_t* spkin = (int8_t*)p_spk;
    int8_t* s1 = (int8_t*)p_s1;
    int8_t* s2 = (int8_t*)p_s2;
    float* mem1 = (float*)p_m1; float* mem2 = (float*)p_m2; float* mem3 = (float*)p_m3;
    float* part = (float*)p_part;
    int8_t *w1a=(int8_t*)p_w1a, *w1b=(int8_t*)p_w1b, *w1c=(int8_t*)p_w1c;
    int8_t *w2a=(int8_t*)p_w2a, *w2b=(int8_t*)p_w2b, *w2c=(int8_t*)p_w2c;
    int8_t *w3a=(int8_t*)p_w3a, *w3b=(int8_t*)p_w3b, *w3c=(int8_t*)p_w3c;

    constexpr int SMEM = 5 * (128 * 128 + 3 * 64 * 128);   // 204800
    static int configured = -1;
    if (configured < 0) {
        cudaFuncSetAttribute(gemm_lif<true>,
                             cudaFuncAttributeMaxDynamicSharedMemorySize, SMEM);
        cudaFuncSetAttribute(gemm_lif<false>,
                             cudaFuncAttributeMaxDynamicSharedMemorySize, SMEM);
        configured = 1;
    }

    // ---- per-call prep: ONE launch ----
    k_prep<<<1184, 256>>>(spike_seq, spkin, TSTEPS * BATCH * INDIM,
                          W1, w1a, w1b, w1c, H1D * INDIM,
                          W2, w2a, w2b, w2c, H2D * H1D,
                          W3, w3a, w3b, w3c, OUTD * H2D,
                          mem1, BATCH * H1D, mem2, BATCH * H2D,
                          mem3, BATCH * OUTD, out, BATCH * OUTD);

    // ---- 50 timesteps ----
    for (int t = 0; t < TSTEPS; ++t) {
        const int8_t* x_t = spkin + (size_t)t * BATCH * INDIM;

        // gemm1; for t>0, z==1 blocks also run the previous step's layer-3
        // reduction + LIF3 + output accumulation
        gemm_lif<true><<<dim3(2, H1D / 64, (t > 0) ? 2 : 1), 256, SMEM>>>(
            x_t, INDIM, w1a, w1b, w1c, INDIM, INDIM / 128,
            b1, mem1, s1, H1D, nullptr,
            part, b3, mem3, out);

        gemm_lif<true><<<dim3(2, H2D / 64, 1), 256, SMEM>>>(
            s1, H1D, w2a, w2b, w2c, H1D, H1D / 128,
            b2, mem2, s2, H2D, nullptr,
            nullptr, nullptr, nullptr, nullptr);

        gemm_lif<false><<<dim3(2, 1, KSPLIT), 256, SMEM>>>(
            s2, H2D, w3a, w3b, w3c, H2D, (H2D / KSPLIT) / 128,
            nullptr, nullptr, nullptr, 0, part,
            nullptr, nullptr, nullptr, nullptr);
    }

    // final step's layer-3 reduction
    k_reduce3<<<(BATCH * OUTD) / 256, 256>>>(part, b3, mem3, out);
}

// round 6
// speedup vs baseline: 3.2407x; 3.2407x over previous
#include <cuda_runtime.h>
#include <cuda_fp16.h>
#include <cstdint>
#include <cstddef>

// ============================================================================
// SNN: 50 timesteps of (GEMM + LIF) x 3 layers, portable sm_103 tensor path:
// mma.sync.m16n8k16 + ldmatrix + cp.async.
// Weights split 2-way into fp16 with scaled residual:
//   w = h + m/256,  h = fp16(w), m = fp16(256*(w-h))
// hi component accumulated in FP32 (mma f32 acc);
// residual component accumulated in FP16 (mma f16 acc, 2x rate) -- its sums
// are tiny (|m| <= w/8), so f16 rounding /256 contributes <1e-6 to the current.
// ============================================================================

#define TSTEPS 50
#define BATCH  256
#define INDIM  1536
#define H1D    4096
#define H2D    4096
#define OUTD   64
#define KSPLIT 32

// ---------------- persistent scratch (device globals) -----------------------
__device__ __align__(128) __half g_spk_in[(size_t)TSTEPS * BATCH * INDIM];
__device__ __align__(128) __half g_s1[(size_t)BATCH * H1D];
__device__ __align__(128) __half g_s2[(size_t)BATCH * H2D];
__device__ __align__(128) float g_mem1[(size_t)BATCH * H1D];
__device__ __align__(128) float g_mem2[(size_t)BATCH * H2D];
__device__ __align__(128) float g_mem3[(size_t)BATCH * OUTD];
__device__ __align__(128) float g_part[(size_t)KSPLIT * BATCH * OUTD];
__device__ __align__(128) __half g_W1a[(size_t)H1D * INDIM];
__device__ __align__(128) __half g_W1b[(size_t)H1D * INDIM];
__device__ __align__(128) __half g_W2a[(size_t)H2D * H1D];
__device__ __align__(128) __half g_W2b[(size_t)H2D * H1D];
__device__ __align__(128) __half g_W3a[(size_t)OUTD * H2D];
__device__ __align__(128) __half g_W3b[(size_t)OUTD * H2D];

// ------------------------------ asm helpers ---------------------------------
__device__ __forceinline__ uint32_t smem_u32(const void* p) {
    uint32_t a;
    asm("{ .reg .u64 t; cvta.to.shared.u64 t, %1; cvt.u32.u64 %0, t; }"
        : "=r"(a) : "l"(p));
    return a;
}

__device__ __forceinline__ void cp16(uint32_t smem, const void* gmem) {
    asm volatile("cp.async.cg.shared.global [%0], [%1], 16;"
                 :: "r"(smem), "l"(gmem) : "memory");
}
__device__ __forceinline__ void cp_commit() {
    asm volatile("cp.async.commit_group;" ::: "memory");
}
template<int N>
__device__ __forceinline__ void cp_wait() {
    asm volatile("cp.async.wait_group %0;" :: "n"(N) : "memory");
}

__device__ __forceinline__ void ldsm4(uint32_t (&r)[4], uint32_t addr) {
    asm volatile("ldmatrix.sync.aligned.m8n8.x4.shared.b16 {%0,%1,%2,%3}, [%4];"
                 : "=r"(r[0]), "=r"(r[1]), "=r"(r[2]), "=r"(r[3]) : "r"(addr));
}

// f32-accumulate HMMA (hi component)
__device__ __forceinline__ void mma_f32(float (&d)[4], const uint32_t (&a)[4],
                                        uint32_t b0, uint32_t b1) {
    asm volatile(
        "mma.sync.aligned.m16n8k16.row.col.f32.f16.f16.f32 "
        "{%0,%1,%2,%3}, {%4,%5,%6,%7}, {%8,%9}, {%0,%1,%2,%3};"
        : "+f"(d[0]), "+f"(d[1]), "+f"(d[2]), "+f"(d[3])
        : "r"(a[0]), "r"(a[1]), "r"(a[2]), "r"(a[3]), "r"(b0), "r"(b1));
}

// f16-accumulate HMMA (residual component, 2x rate)
__device__ __forceinline__ void mma_f16(uint32_t (&d)[2], const uint32_t (&a)[4],
                                        uint32_t b0, uint32_t b1) {
    asm volatile(
        "mma.sync.aligned.m16n8k16.row.col.f16.f16.f16.f16 "
        "{%0,%1}, {%2,%3,%4,%5}, {%6,%7}, {%0,%1};"
        : "+r"(d[0]), "+r"(d[1])
        : "r"(a[0]), "r"(a[1]), "r"(a[2]), "r"(a[3]), "r"(b0), "r"(b1));
}

// ============================================================================
// GEMM (+ LIF epilogue or split-K partial store).
//   D[m,n] = sum_k A[m0+m,k] * (Wa + Wb/256)[n0+n,k],  k in [kbase, kbase+nk*64)
// CTA: M=128 x N=64, 256 threads, warps 4(m) x 2(n), warp tile 32x32.
// 5-stage cp.async ring; stage = A(128x64 f16) + 2x W(64x64 f16) = 32KB.
// For LIF kernels, blockIdx.z==1 blocks instead perform the previous step's
// layer-3 split-K reduction + LIF3 + output accumulation (launch fusion).
// ============================================================================
template<bool LIF>
__global__ void __launch_bounds__(256, 1) gemm_lif(
    const __half* __restrict__ A, int lda,
    const __half* __restrict__ Wa,
    const __half* __restrict__ Wb,
    int ldw, int nk,
    const float* __restrict__ bias,
    float* __restrict__ memv,
    __half* __restrict__ spk, int ldn,
    float* __restrict__ part,
    const float* __restrict__ r_part,
    const float* __restrict__ r_b3,
    float* __restrict__ r_mem3,
    float* __restrict__ r_out)
{
    constexpr int S = 5;
    constexpr int ABYTES = 128 * 128;          // 16KB: 128 rows x 64 f16
    constexpr int BCOMP  = 64 * 128;           // 8KB per weight component
    constexpr int STAGE  = ABYTES + 2 * BCOMP; // 32KB

    const int tid = threadIdx.x;

    // ---- fused reduce blocks (previous step's layer-3 epilogue) -------------
    if (LIF && blockIdx.z == 1) {
        const int bid = (int)(blockIdx.y * 2 + blockIdx.x);
        if (bid < (BATCH * OUTD) / 256) {
            const int idx = bid * 256 + tid;
            const int n = idx & (OUTD - 1);
            float s = r_b3[n];
            #pragma unroll
            for (int zz = 0; zz < KSPLIT; ++zz)
                s += r_part[(size_t)zz * BATCH * OUTD + idx];
            const float mo = r_mem3[idx];
            const float mn = 0.9f * mo + s - ((mo > 1.0f) ? 1.0f : 0.0f);
            r_mem3[idx] = mn;
            r_out[idx] += ((mn > 1.0f) ? 1.0f : 0.0f);
        }
        return;
    }

    extern __shared__ char smem[];
    const uint32_t sbase = smem_u32(smem);

    const int lane = tid & 31;
    const int wid  = tid >> 5;
    const int m0   = blockIdx.x * 128;
    const int n0   = blockIdx.y * 64;
    const int z    = blockIdx.z;
    const int kbase = LIF ? 0 : z * nk * 64;

    const int warp_m = (wid >> 1) * 32;  // 0,32,64,96
    const int warp_n = (wid & 1) * 32;   // 0,32

    // ---- stage loader -------------------------------------------------------
    auto load_stage = [&](int L) {
        if (L >= nk) return;
        const uint32_t st = sbase + (uint32_t)(L % S) * STAGE;
        const int k0 = kbase + L * 64;
        // A: 1024 16B-slots, 4 per thread
        #pragma unroll
        for (int i = 0; i < 4; ++i) {
            const int idx  = tid + i * 256;
            const int row  = idx >> 3;
            const int slot = idx & 7;
            const char* g = (const char*)(A + (size_t)(m0 + row) * lda + k0) + slot * 16;
            cp16(st + (uint32_t)row * 128u + (uint32_t)((slot ^ (row & 7)) << 4), g);
        }
        // B: 2 comps x 512 slots, 2 per thread per comp
        #pragma unroll
        for (int c = 0; c < 2; ++c) {
            const __half* W = (c == 0) ? Wa : Wb;
            const uint32_t bb = st + ABYTES + (uint32_t)c * BCOMP;
            #pragma unroll
            for (int i = 0; i < 2; ++i) {
                const int idx  = tid + i * 256;
                const int row  = idx >> 3;
                const int slot = idx & 7;
                const char* g = (const char*)(W + (size_t)(n0 + row) * ldw + k0) + slot * 16;
                cp16(bb + (uint32_t)row * 128u + (uint32_t)((slot ^ (row & 7)) << 4), g);
            }
        }
    };

    // ---- pipeline prologue ---------------------------------------------------
    #pragma unroll
    for (int L = 0; L < S - 1; ++L) { load_stage(L); cp_commit(); }

    float    acc [2][4][4];   // hi comp, f32 acc
    uint32_t accr[2][4][2];   // res comp, f16x2 acc
    #pragma unroll
    for (int mt = 0; mt < 2; ++mt)
        #pragma unroll
        for (int nt = 0; nt < 4; ++nt) {
            #pragma unroll
            for (int e = 0; e < 4; ++e) acc[mt][nt][e] = 0.0f;
            accr[mt][nt][0] = 0u; accr[mt][nt][1] = 0u;
        }

    const int a_row = (lane & 7) | (((lane >> 3) & 1) << 3);
    const int a_sel = lane >> 4;
    const int b_row = (lane & 7) | (((lane >> 4) & 1) << 3);
    const int b_sel = (lane >> 3) & 1;

    // ---- main loop ------------------------------------------------------------
    for (int it = 0; it < nk; ++it) {
        cp_wait<S - 2>();
        __syncthreads();
        load_stage(it + S - 1);
        cp_commit();

        const uint32_t st = sbase + (uint32_t)(it % S) * STAGE;

        uint32_t afr[2][4][4];
        #pragma unroll
        for (int mt = 0; mt < 2; ++mt) {
            #pragma unroll
            for (int kk = 0; kk < 4; ++kk) {
                const int row  = warp_m + mt * 16 + a_row;
                const int slot = kk * 2 + a_sel;
                ldsm4(afr[mt][kk],
                      st + (uint32_t)row * 128u + (uint32_t)((slot ^ (row & 7)) << 4));
            }
        }

        // ---- hi component (f32 acc) ----
        {
            const uint32_t bb = st + ABYTES;
            uint32_t bfr[4][2][4];
            #pragma unroll
            for (int kk = 0; kk < 4; ++kk) {
                #pragma unroll
                for (int jn = 0; jn < 2; ++jn) {
                    const int row  = warp_n + jn * 16 + b_row;
                    const int slot = kk * 2 + b_sel;
                    ldsm4(bfr[kk][jn],
                          bb + (uint32_t)row * 128u + (uint32_t)((slot ^ (row & 7)) << 4));
                }
            }
            #pragma unroll
            for (int kk = 0; kk < 4; ++kk)
                #pragma unroll
                for (int mt = 0; mt < 2; ++mt)
                    #pragma unroll
                    for (int nt = 0; nt < 4; ++nt)
                        mma_f32(acc[mt][nt], afr[mt][kk],
                                bfr[kk][nt >> 1][(nt & 1) * 2],
                                bfr[kk][nt >> 1][(nt & 1) * 2 + 1]);
        }

        // ---- residual component (f16 acc, 2x rate) ----
        {
            const uint32_t bb = st + ABYTES + BCOMP;
            uint32_t bfr[4][2][4];
            #pragma unroll
            for (int kk = 0; kk < 4; ++kk) {
                #pragma unroll
                for (int jn = 0; jn < 2; ++jn) {
                    const int row  = warp_n + jn * 16 + b_row;
                    const int slot = kk * 2 + b_sel;
                    ldsm4(bfr[kk][jn],
                          bb + (uint32_t)row * 128u + (uint32_t)((slot ^ (row & 7)) << 4));
                }
            }
            #pragma unroll
            for (int kk = 0; kk < 4; ++kk)
                #pragma unroll
                for (int mt = 0; mt < 2; ++mt)
                    #pragma unroll
                    for (int nt = 0; nt < 4; ++nt)
                        mma_f16(accr[mt][nt], afr[mt][kk],
                                bfr[kk][nt >> 1][(nt & 1) * 2],
                                bfr[kk][nt >> 1][(nt & 1) * 2 + 1]);
        }
    }

    // ---- epilogue -------------------------------------------------------------
    constexpr float SC = 1.0f / 256.0f;
    const int col2 = (lane & 3) * 2;
    const int rowg = lane >> 2;
    #pragma unroll
    for (int mt = 0; mt < 2; ++mt) {
        #pragma unroll
        for (int nt = 0; nt < 4; ++nt) {
            const int n = n0 + warp_n + nt * 8 + col2;
            const int mbase = m0 + warp_m + mt * 16 + rowg;
            // unpack residual f16 accumulators: reg0 = (e0,e1), reg1 = (e2,e3)
            const float2 r01 = __half22float2(*(const __half2*)&accr[mt][nt][0]);
            const float2 r23 = __half22float2(*(const __half2*)&accr[mt][nt][1]);
            float cur[4];
            cur[0] = acc[mt][nt][0] + SC * r01.x;
            cur[1] = acc[mt][nt][1] + SC * r01.y;
            cur[2] = acc[mt][nt][2] + SC * r23.x;
            cur[3] = acc[mt][nt][3] + SC * r23.y;
            if (LIF) {
                const float2 bv = *(const float2*)(bias + n);
                #pragma unroll
                for (int h = 0; h < 2; ++h) {
                    const int m = mbase + h * 8;
                    const size_t off = (size_t)m * ldn + n;
                    float2 mo = *(float2*)(memv + off);
                    const float c0 = cur[h * 2 + 0] + bv.x;
                    const float c1 = cur[h * 2 + 1] + bv.y;
                    const float mn0 = 0.9f * mo.x + c0 - ((mo.x > 1.0f) ? 1.0f : 0.0f);
                    const float mn1 = 0.9f * mo.y + c1 - ((mo.y > 1.0f) ? 1.0f : 0.0f);
                    float2 mw; mw.x = mn0; mw.y = mn1;
                    *(float2*)(memv + off) = mw;
                    __half2 sv;
                    sv.x = __float2half((mn0 > 1.0f) ? 1.0f : 0.0f);
                    sv.y = __float2half((mn1 > 1.0f) ? 1.0f : 0.0f);
                    *(__half2*)(spk + off) = sv;
                }
            } else {
                float* po = part + (size_t)z * BATCH * OUTD;
                #pragma unroll
                for (int h = 0; h < 2; ++h) {
                    const int m = mbase + h * 8;
                    float2 pv; pv.x = cur[h * 2 + 0]; pv.y = cur[h * 2 + 1];
                    *(float2*)(po + (size_t)m * OUTD + n) = pv;
                }
            }
        }
    }
}

// ============================================================================
// Single prep kernel: spike convert + weight splits + state zeroing (1 launch)
// ============================================================================
__device__ __forceinline__ void split_one(const float* __restrict__ W,
                                          __half* __restrict__ a,
                                          __half* __restrict__ b,
                                          int n, int gid, int st) {
    for (int i = gid; i < n; i += st) {
        const float w = W[i];
        const __half h = __float2half_rn(w);
        const float r = w - __half2float(h);
        a[i] = h;
        b[i] = __float2half_rn(r * 256.0f);
    }
}

__global__ void k_prep(const float* __restrict__ x, __half* __restrict__ xs, int nx,
                       const float* __restrict__ W1, __half* w1a, __half* w1b, int n1,
                       const float* __restrict__ W2, __half* w2a, __half* w2b, int n2,
                       const float* __restrict__ W3, __half* w3a, __half* w3b, int n3,
                       float* __restrict__ z1, int nz1,
                       float* __restrict__ z2, int nz2,
                       float* __restrict__ z3, int nz3,
                       float* __restrict__ z4, int nz4) {
    const int gid = blockIdx.x * blockDim.x + threadIdx.x;
    const int st  = gridDim.x * blockDim.x;
    for (int i = gid; i < nx; i += st) xs[i] = __float2half(x[i]);
    split_one(W1, w1a, w1b, n1, gid, st);
    split_one(W2, w2a, w2b, n2, gid, st);
    split_one(W3, w3a, w3b, n3, gid, st);
    for (int i = gid; i < nz1; i += st) z1[i] = 0.0f;
    for (int i = gid; i < nz2; i += st) z2[i] = 0.0f;
    for (int i = gid; i < nz3; i += st) z3[i] = 0.0f;
    for (int i = gid; i < nz4; i += st) z4[i] = 0.0f;
}

__global__ void k_reduce3(const float* __restrict__ part,
                          const float* __restrict__ b3,
                          float* __restrict__ mem3,
                          float* __restrict__ out) {
    const int idx = blockIdx.x * blockDim.x + threadIdx.x;   // 16384 threads exact
    const int n = idx & (OUTD - 1);
    float s = b3[n];
    #pragma unroll
    for (int zz = 0; zz < KSPLIT; ++zz)
        s += part[(size_t)zz * BATCH * OUTD + idx];
    const float mo = mem3[idx];
    const float mn = 0.9f * mo + s - ((mo > 1.0f) ? 1.0f : 0.0f);
    mem3[idx] = mn;
    out[idx] += ((mn > 1.0f) ? 1.0f : 0.0f);
}

// ============================================================================
// Host launcher
// ============================================================================
extern "C" void kernel_launch(void* const* d_in, const int* in_sizes, int n_in,
                              void* d_out, int out_size) {
    (void)in_sizes; (void)n_in; (void)out_size;

    const float* spike_seq = (const float*)d_in[0];
    const float* W1 = (const float*)d_in[1];
    const float* b1 = (const float*)d_in[2];
    const float* W2 = (const float*)d_in[3];
    const float* b2 = (const float*)d_in[4];
    const float* W3 = (const float*)d_in[5];
    const float* b3 = (const float*)d_in[6];
    float* out = (float*)d_out;

    void *p_spk, *p_s1, *p_s2, *p_m1, *p_m2, *p_m3, *p_part;
    void *p_w1a, *p_w1b, *p_w2a, *p_w2b, *p_w3a, *p_w3b;
    cudaGetSymbolAddress(&p_spk, g_spk_in);
    cudaGetSymbolAddress(&p_s1, g_s1);   cudaGetSymbolAddress(&p_s2, g_s2);
    cudaGetSymbolAddress(&p_m1, g_mem1); cudaGetSymbolAddress(&p_m2, g_mem2);
    cudaGetSymbolAddress(&p_m3, g_mem3); cudaGetSymbolAddress(&p_part, g_part);
    cudaGetSymbolAddress(&p_w1a, g_W1a); cudaGetSymbolAddress(&p_w1b, g_W1b);
    cudaGetSymbolAddress(&p_w2a, g_W2a); cudaGetSymbolAddress(&p_w2b, g_W2b);
    cudaGetSymbolAddress(&p_w3a, g_W3a); cudaGetSymbolAddress(&p_w3b, g_W3b);

    __half* spkin = (__half*)p_spk;
    __half* s1 = (__half*)p_s1;
    __half* s2 = (__half*)p_s2;
    float* mem1 = (float*)p_m1; float* mem2 = (float*)p_m2; float* mem3 = (float*)p_m3;
    float* part = (float*)p_part;
    __half *w1a = (__half*)p_w1a, *w1b = (__half*)p_w1b;
    __half *w2a = (__half*)p_w2a, *w2b = (__half*)p_w2b;
    __half *w3a = (__half*)p_w3a, *w3b = (__half*)p_w3b;

    constexpr int SMEM = 5 * (128 * 128 + 2 * 64 * 128);   // 163840
    static int configured = -1;
    if (configured < 0) {
        cudaFuncSetAttribute(gemm_lif<true>,
                             cudaFuncAttributeMaxDynamicSharedMemorySize, SMEM);
        cudaFuncSetAttribute(gemm_lif<false>,
                             cudaFuncAttributeMaxDynamicSharedMemorySize, SMEM);
        configured = 1;
    }

    // ---- per-call prep: ONE launch ----
    k_prep<<<1184, 256>>>(spike_seq, spkin, TSTEPS * BATCH * INDIM,
                          W1, w1a, w1b, H1D * INDIM,
                          W2, w2a, w2b, H2D * H1D,
                          W3, w3a, w3b, OUTD * H2D,
                          mem1, BATCH * H1D, mem2, BATCH * H2D,
                          mem3, BATCH * OUTD, out, BATCH * OUTD);

    // ---- 50 timesteps ----
    for (int t = 0; t < TSTEPS; ++t) {
        const __half* x_t = spkin + (size_t)t * BATCH * INDIM;

        // gemm1; for t>0, z==1 blocks also run the previous step's layer-3
        // reduction + LIF3 + output accumulation
        gemm_lif<true><<<dim3(2, H1D / 64, (t > 0) ? 2 : 1), 256, SMEM>>>(
            x_t, INDIM, w1a, w1b, INDIM, INDIM / 64,
            b1, mem1, s1, H1D, nullptr,
            part, b3, mem3, out);

        gemm_lif<true><<<dim3(2, H2D / 64, 1), 256, SMEM>>>(
            s1, H1D, w2a, w2b, H1D, H1D / 64,
            b2, mem2, s2, H2D, nullptr,
            nullptr, nullptr, nullptr, nullptr);

        gemm_lif<false><<<dim3(2, 1, KSPLIT), 256, SMEM>>>(
            s2, H2D, w3a, w3b, H2D, (H2D / KSPLIT) / 64,
            nullptr, nullptr, nullptr, 0, part,
            nullptr, nullptr, nullptr, nullptr);
    }

    // final step's layer-3 reduction
    k_reduce3<<<(BATCH * OUTD) / 256, 256>>>(part, b3, mem3, out);
}

// round 7
// speedup vs baseline: 3.6239x; 1.1182x over previous
#include <cuda_runtime.h>
#include <cuda_fp16.h>
#include <cstdint>
#include <cstddef>

// ============================================================================
// SNN: 50 timesteps of (GEMM + LIF) x 3 layers, portable sm_103 tensor path:
// mma.sync.m16n8k16 + ldmatrix + cp.async.
// Weights split 2-way into fp16 with scaled residual:
//   w = h + m/256,  h = fp16(w), m = fp16(256*(w-h))
// hi component accumulated in FP32; residual in FP16 acc (validated: rel_err 0).
// Pipeline: K-chunk 128 per stage (two 64-halves), S=3, 192KB smem, 1 CTA/SM.
// ============================================================================

#define TSTEPS 50
#define BATCH  256
#define INDIM  1536
#define H1D    4096
#define H2D    4096
#define OUTD   64
#define KSPLIT 32

// ---------------- persistent scratch (device globals) -----------------------
__device__ __align__(128) __half g_spk_in[(size_t)TSTEPS * BATCH * INDIM];
__device__ __align__(128) __half g_s1[(size_t)BATCH * H1D];
__device__ __align__(128) __half g_s2[(size_t)BATCH * H2D];
__device__ __align__(128) float g_mem1[(size_t)BATCH * H1D];
__device__ __align__(128) float g_mem2[(size_t)BATCH * H2D];
__device__ __align__(128) float g_mem3[(size_t)BATCH * OUTD];
__device__ __align__(128) float g_part[(size_t)KSPLIT * BATCH * OUTD];
__device__ __align__(128) __half g_W1a[(size_t)H1D * INDIM];
__device__ __align__(128) __half g_W1b[(size_t)H1D * INDIM];
__device__ __align__(128) __half g_W2a[(size_t)H2D * H1D];
__device__ __align__(128) __half g_W2b[(size_t)H2D * H1D];
__device__ __align__(128) __half g_W3a[(size_t)OUTD * H2D];
__device__ __align__(128) __half g_W3b[(size_t)OUTD * H2D];

// ------------------------------ asm helpers ---------------------------------
__device__ __forceinline__ uint32_t smem_u32(const void* p) {
    uint32_t a;
    asm("{ .reg .u64 t; cvta.to.shared.u64 t, %1; cvt.u32.u64 %0, t; }"
        : "=r"(a) : "l"(p));
    return a;
}

__device__ __forceinline__ void cp16(uint32_t smem, const void* gmem) {
    asm volatile("cp.async.cg.shared.global [%0], [%1], 16;"
                 :: "r"(smem), "l"(gmem) : "memory");
}
__device__ __forceinline__ void cp_commit() {
    asm volatile("cp.async.commit_group;" ::: "memory");
}
template<int N>
__device__ __forceinline__ void cp_wait() {
    asm volatile("cp.async.wait_group %0;" :: "n"(N) : "memory");
}

__device__ __forceinline__ void ldsm4(uint32_t (&r)[4], uint32_t addr) {
    asm volatile("ldmatrix.sync.aligned.m8n8.x4.shared.b16 {%0,%1,%2,%3}, [%4];"
                 : "=r"(r[0]), "=r"(r[1]), "=r"(r[2]), "=r"(r[3]) : "r"(addr));
}

// f32-accumulate HMMA (hi component)
__device__ __forceinline__ void mma_f32(float (&d)[4], const uint32_t (&a)[4],
                                        uint32_t b0, uint32_t b1) {
    asm volatile(
        "mma.sync.aligned.m16n8k16.row.col.f32.f16.f16.f32 "
        "{%0,%1,%2,%3}, {%4,%5,%6,%7}, {%8,%9}, {%0,%1,%2,%3};"
        : "+f"(d[0]), "+f"(d[1]), "+f"(d[2]), "+f"(d[3])
        : "r"(a[0]), "r"(a[1]), "r"(a[2]), "r"(a[3]), "r"(b0), "r"(b1));
}

// f16-accumulate HMMA (residual component)
__device__ __forceinline__ void mma_f16(uint32_t (&d)[2], const uint32_t (&a)[4],
                                        uint32_t b0, uint32_t b1) {
    asm volatile(
        "mma.sync.aligned.m16n8k16.row.col.f16.f16.f16.f16 "
        "{%0,%1}, {%2,%3,%4,%5}, {%6,%7}, {%0,%1};"
        : "+r"(d[0]), "+r"(d[1])
        : "r"(a[0]), "r"(a[1]), "r"(a[2]), "r"(a[3]), "r"(b0), "r"(b1));
}

// ============================================================================
// GEMM (+ LIF epilogue or split-K partial store).
//   D[m,n] = sum_k A[m0+m,k] * (Wa + Wb/256)[n0+n,k],  k in [kbase, kbase+nk*128)
// CTA: M=128 x N=64, 256 threads, warps 4(m) x 2(n), warp tile 32x32.
// 3-stage cp.async ring; stage = K-chunk 128 stored as two 64-halves:
//   A: 2 x 16KB, B: 2 comps x 2 x 8KB  -> 64KB/stage, 192KB total.
// LIF kernels with gridDim.y > 64: blocks with by >= 64 run the previous
// step's layer-3 split-K reduction + LIF3 + output accumulation (same wave).
// ============================================================================
template<bool LIF>
__global__ void __launch_bounds__(256, 1) gemm_lif(
    const __half* __restrict__ A, int lda,
    const __half* __restrict__ Wa,
    const __half* __restrict__ Wb,
    int ldw, int nk,
    const float* __restrict__ bias,
    float* __restrict__ memv,
    __half* __restrict__ spk, int ldn,
    float* __restrict__ part,
    const float* __restrict__ r_part,
    const float* __restrict__ r_b3,
    float* __restrict__ r_mem3,
    float* __restrict__ r_out)
{
    constexpr int S = 3;
    constexpr int AHALF  = 128 * 128;            // 16KB: 128 rows x 64 f16
    constexpr int ABYTES = 2 * AHALF;            // 32KB
    constexpr int BHALF  = 64 * 128;             // 8KB
    constexpr int BCOMP  = 2 * BHALF;            // 16KB per weight component
    constexpr int STAGE  = ABYTES + 2 * BCOMP;   // 64KB

    const int tid = threadIdx.x;

    // ---- fused reduce blocks (previous step's layer-3 epilogue) -------------
    if (LIF && blockIdx.y >= 64) {
        const int rblk = ((int)blockIdx.y - 64) * 2 + (int)blockIdx.x;  // 0..15
        const int base = rblk * 1024;
        #pragma unroll
        for (int j = 0; j < 4; ++j) {
            const int idx = base + j * 256 + tid;
            const int n = idx & (OUTD - 1);
            float s = r_b3[n];
            #pragma unroll
            for (int zz = 0; zz < KSPLIT; ++zz)
                s += r_part[(size_t)zz * BATCH * OUTD + idx];
            const float mo = r_mem3[idx];
            const float mn = 0.9f * mo + s - ((mo > 1.0f) ? 1.0f : 0.0f);
            r_mem3[idx] = mn;
            r_out[idx] += ((mn > 1.0f) ? 1.0f : 0.0f);
        }
        return;
    }

    extern __shared__ char smem[];
    const uint32_t sbase = smem_u32(smem);

    const int lane = tid & 31;
    const int wid  = tid >> 5;
    const int m0   = blockIdx.x * 128;
    const int n0   = blockIdx.y * 64;
    const int z    = blockIdx.z;
    const int kbase = LIF ? 0 : z * nk * 128;

    const int warp_m = (wid >> 1) * 32;  // 0,32,64,96
    const int warp_n = (wid & 1) * 32;   // 0,32

    // ---- stage loader: K-chunk 128 as two 64-halves --------------------------
    auto load_stage = [&](int L) {
        if (L >= nk) return;
        const uint32_t st = sbase + (uint32_t)(L % S) * STAGE;
        const int k0 = kbase + L * 128;
        #pragma unroll
        for (int h = 0; h < 2; ++h) {
            const int kh = k0 + h * 64;
            // A half: 1024 16B-slots, 4 per thread
            #pragma unroll
            for (int i = 0; i < 4; ++i) {
                const int idx  = tid + i * 256;
                const int row  = idx >> 3;
                const int slot = idx & 7;
                const char* g = (const char*)(A + (size_t)(m0 + row) * lda + kh) + slot * 16;
                cp16(st + (uint32_t)h * AHALF + (uint32_t)row * 128u
                        + (uint32_t)((slot ^ (row & 7)) << 4), g);
            }
            // B halves: 2 comps x 512 slots, 2 per thread per comp
            #pragma unroll
            for (int c = 0; c < 2; ++c) {
                const __half* W = (c == 0) ? Wa : Wb;
                const uint32_t bb = st + ABYTES + (uint32_t)c * BCOMP + (uint32_t)h * BHALF;
                #pragma unroll
                for (int i = 0; i < 2; ++i) {
                    const int idx  = tid + i * 256;
                    const int row  = idx >> 3;
                    const int slot = idx & 7;
                    const char* g = (const char*)(W + (size_t)(n0 + row) * ldw + kh) + slot * 16;
                    cp16(bb + (uint32_t)row * 128u
                            + (uint32_t)((slot ^ (row & 7)) << 4), g);
                }
            }
        }
    };

    // ---- pipeline prologue ---------------------------------------------------
    #pragma unroll
    for (int L = 0; L < S - 1; ++L) { load_stage(L); cp_commit(); }

    float    acc [2][4][4];   // hi comp, f32 acc
    uint32_t accr[2][4][2];   // res comp, f16x2 acc
    #pragma unroll
    for (int mt = 0; mt < 2; ++mt)
        #pragma unroll
        for (int nt = 0; nt < 4; ++nt) {
            #pragma unroll
            for (int e = 0; e < 4; ++e) acc[mt][nt][e] = 0.0f;
            accr[mt][nt][0] = 0u; accr[mt][nt][1] = 0u;
        }

    const int a_row = (lane & 7) | (((lane >> 3) & 1) << 3);
    const int a_sel = lane >> 4;
    const int b_row = (lane & 7) | (((lane >> 4) & 1) << 3);
    const int b_sel = (lane >> 3) & 1;

    // ---- main loop ------------------------------------------------------------
    for (int it = 0; it < nk; ++it) {
        cp_wait<S - 2>();
        __syncthreads();
        load_stage(it + S - 1);
        cp_commit();

        const uint32_t st = sbase + (uint32_t)(it % S) * STAGE;

        #pragma unroll
        for (int h = 0; h < 2; ++h) {
            const uint32_t ah = st + (uint32_t)h * AHALF;

            uint32_t afr[2][4][4];
            #pragma unroll
            for (int mt = 0; mt < 2; ++mt) {
                #pragma unroll
                for (int kk = 0; kk < 4; ++kk) {
                    const int row  = warp_m + mt * 16 + a_row;
                    const int slot = kk * 2 + a_sel;
                    ldsm4(afr[mt][kk],
                          ah + (uint32_t)row * 128u + (uint32_t)((slot ^ (row & 7)) << 4));
                }
            }

            // ---- hi component (f32 acc) ----
            {
                const uint32_t bb = st + ABYTES + (uint32_t)h * BHALF;
                uint32_t bfr[4][2][4];
                #pragma unroll
                for (int kk = 0; kk < 4; ++kk) {
                    #pragma unroll
                    for (int jn = 0; jn < 2; ++jn) {
                        const int row  = warp_n + jn * 16 + b_row;
                        const int slot = kk * 2 + b_sel;
                        ldsm4(bfr[kk][jn],
                              bb + (uint32_t)row * 128u + (uint32_t)((slot ^ (row & 7)) << 4));
                    }
                }
                #pragma unroll
                for (int kk = 0; kk < 4; ++kk)
                    #pragma unroll
                    for (int mt = 0; mt < 2; ++mt)
                        #pragma unroll
                        for (int nt = 0; nt < 4; ++nt)
                            mma_f32(acc[mt][nt], afr[mt][kk],
                                    bfr[kk][nt >> 1][(nt & 1) * 2],
                                    bfr[kk][nt >> 1][(nt & 1) * 2 + 1]);
            }

            // ---- residual component (f16 acc) ----
            {
                const uint32_t bb = st + ABYTES + BCOMP + (uint32_t)h * BHALF;
                uint32_t bfr[4][2][4];
                #pragma unroll
                for (int kk = 0; kk < 4; ++kk) {
                    #pragma unroll
                    for (int jn = 0; jn < 2; ++jn) {
                        const int row  = warp_n + jn * 16 + b_row;
                        const int slot = kk * 2 + b_sel;
                        ldsm4(bfr[kk][jn],
                              bb + (uint32_t)row * 128u + (uint32_t)((slot ^ (row & 7)) << 4));
                    }
                }
                #pragma unroll
                for (int kk = 0; kk < 4; ++kk)
                    #pragma unroll
                    for (int mt = 0; mt < 2; ++mt)
                        #pragma unroll
                        for (int nt = 0; nt < 4; ++nt)
                            mma_f16(accr[mt][nt], afr[mt][kk],
                                    bfr[kk][nt >> 1][(nt & 1) * 2],
                                    bfr[kk][nt >> 1][(nt & 1) * 2 + 1]);
            }
        }
    }

    // ---- epilogue -------------------------------------------------------------
    constexpr float SC = 1.0f / 256.0f;
    const int col2 = (lane & 3) * 2;
    const int rowg = lane >> 2;
    #pragma unroll
    for (int mt = 0; mt < 2; ++mt) {
        #pragma unroll
        for (int nt = 0; nt < 4; ++nt) {
            const int n = n0 + warp_n + nt * 8 + col2;
            const int mbase = m0 + warp_m + mt * 16 + rowg;
            const float2 r01 = __half22float2(*(const __half2*)&accr[mt][nt][0]);
            const float2 r23 = __half22float2(*(const __half2*)&accr[mt][nt][1]);
            float cur[4];
            cur[0] = acc[mt][nt][0] + SC * r01.x;
            cur[1] = acc[mt][nt][1] + SC * r01.y;
            cur[2] = acc[mt][nt][2] + SC * r23.x;
            cur[3] = acc[mt][nt][3] + SC * r23.y;
            if (LIF) {
                const float2 bv = *(const float2*)(bias + n);
                #pragma unroll
                for (int h = 0; h < 2; ++h) {
                    const int m = mbase + h * 8;
                    const size_t off = (size_t)m * ldn + n;
                    float2 mo = *(float2*)(memv + off);
                    const float c0 = cur[h * 2 + 0] + bv.x;
                    const float c1 = cur[h * 2 + 1] + bv.y;
                    const float mn0 = 0.9f * mo.x + c0 - ((mo.x > 1.0f) ? 1.0f : 0.0f);
                    const float mn1 = 0.9f * mo.y + c1 - ((mo.y > 1.0f) ? 1.0f : 0.0f);
                    float2 mw; mw.x = mn0; mw.y = mn1;
                    *(float2*)(memv + off) = mw;
                    __half2 sv;
                    sv.x = __float2half((mn0 > 1.0f) ? 1.0f : 0.0f);
                    sv.y = __float2half((mn1 > 1.0f) ? 1.0f : 0.0f);
                    *(__half2*)(spk + off) = sv;
                }
            } else {
                float* po = part + (size_t)z * BATCH * OUTD;
                #pragma unroll
                for (int h = 0; h < 2; ++h) {
                    const int m = mbase + h * 8;
                    float2 pv; pv.x = cur[h * 2 + 0]; pv.y = cur[h * 2 + 1];
                    *(float2*)(po + (size_t)m * OUTD + n) = pv;
                }
            }
        }
    }
}

// ============================================================================
// Single prep kernel: spike convert + weight splits + state zeroing (1 launch)
// ============================================================================
__device__ __forceinline__ void split_one(const float* __restrict__ W,
                                          __half* __restrict__ a,
                                          __half* __restrict__ b,
                                          int n, int gid, int st) {
    for (int i = gid; i < n; i += st) {
        const float w = W[i];
        const __half h = __float2half_rn(w);
        const float r = w - __half2float(h);
        a[i] = h;
        b[i] = __float2half_rn(r * 256.0f);
    }
}

__global__ void k_prep(const float* __restrict__ x, __half* __restrict__ xs, int nx,
                       const float* __restrict__ W1, __half* w1a, __half* w1b, int n1,
                       const float* __restrict__ W2, __half* w2a, __half* w2b, int n2,
                       const float* __restrict__ W3, __half* w3a, __half* w3b, int n3,
                       float* __restrict__ z1, int nz1,
                       float* __restrict__ z2, int nz2,
                       float* __restrict__ z3, int nz3,
                       float* __restrict__ z4, int nz4) {
    const int gid = blockIdx.x * blockDim.x + threadIdx.x;
    const int st  = gridDim.x * blockDim.x;
    for (int i = gid; i < nx; i += st) xs[i] = __float2half(x[i]);
    split_one(W1, w1a, w1b, n1, gid, st);
    split_one(W2, w2a, w2b, n2, gid, st);
    split_one(W3, w3a, w3b, n3, gid, st);
    for (int i = gid; i < nz1; i += st) z1[i] = 0.0f;
    for (int i = gid; i < nz2; i += st) z2[i] = 0.0f;
    for (int i = gid; i < nz3; i += st) z3[i] = 0.0f;
    for (int i = gid; i < nz4; i += st) z4[i] = 0.0f;
}

__global__ void k_reduce3(const float* __restrict__ part,
                          const float* __restrict__ b3,
                          float* __restrict__ mem3,
                          float* __restrict__ out) {
    const int idx = blockIdx.x * blockDim.x + threadIdx.x;   // 16384 threads exact
    const int n = idx & (OUTD - 1);
    float s = b3[n];
    #pragma unroll
    for (int zz = 0; zz < KSPLIT; ++zz)
        s += part[(size_t)zz * BATCH * OUTD + idx];
    const float mo = mem3[idx];
    const float mn = 0.9f * mo + s - ((mo > 1.0f) ? 1.0f : 0.0f);
    mem3[idx] = mn;
    out[idx] += ((mn > 1.0f) ? 1.0f : 0.0f);
}

// ============================================================================
// Host launcher
// ============================================================================
extern "C" void kernel_launch(void* const* d_in, const int* in_sizes, int n_in,
                              void* d_out, int out_size) {
    (void)in_sizes; (void)n_in; (void)out_size;

    const float* spike_seq = (const float*)d_in[0];
    const float* W1 = (const float*)d_in[1];
    const float* b1 = (const float*)d_in[2];
    const float* W2 = (const float*)d_in[3];
    const float* b2 = (const float*)d_in[4];
    const float* W3 = (const float*)d_in[5];
    const float* b3 = (const float*)d_in[6];
    float* out = (float*)d_out;

    void *p_spk, *p_s1, *p_s2, *p_m1, *p_m2, *p_m3, *p_part;
    void *p_w1a, *p_w1b, *p_w2a, *p_w2b, *p_w3a, *p_w3b;
    cudaGetSymbolAddress(&p_spk, g_spk_in);
    cudaGetSymbolAddress(&p_s1, g_s1);   cudaGetSymbolAddress(&p_s2, g_s2);
    cudaGetSymbolAddress(&p_m1, g_mem1); cudaGetSymbolAddress(&p_m2, g_mem2);
    cudaGetSymbolAddress(&p_m3, g_mem3); cudaGetSymbolAddress(&p_part, g_part);
    cudaGetSymbolAddress(&p_w1a, g_W1a); cudaGetSymbolAddress(&p_w1b, g_W1b);
    cudaGetSymbolAddress(&p_w2a, g_W2a); cudaGetSymbolAddress(&p_w2b, g_W2b);
    cudaGetSymbolAddress(&p_w3a, g_W3a); cudaGetSymbolAddress(&p_w3b, g_W3b);

    __half* spkin = (__half*)p_spk;
    __half* s1 = (__half*)p_s1;
    __half* s2 = (__half*)p_s2;
    float* mem1 = (float*)p_m1; float* mem2 = (float*)p_m2; float* mem3 = (float*)p_m3;
    float* part = (float*)p_part;
    __half *w1a = (__half*)p_w1a, *w1b = (__half*)p_w1b;
    __half *w2a = (__half*)p_w2a, *w2b = (__half*)p_w2b;
    __half *w3a = (__half*)p_w3a, *w3b = (__half*)p_w3b;

    constexpr int SMEM = 3 * (2 * 128 * 128 + 2 * 2 * 64 * 128);   // 196608
    static int configured = -1;
    if (configured < 0) {
        cudaFuncSetAttribute(gemm_lif<true>,
                             cudaFuncAttributeMaxDynamicSharedMemorySize, SMEM);
        cudaFuncSetAttribute(gemm_lif<false>,
                             cudaFuncAttributeMaxDynamicSharedMemorySize, SMEM);
        configured = 1;
    }

    // ---- per-call prep: ONE launch ----
    k_prep<<<1184, 256>>>(spike_seq, spkin, TSTEPS * BATCH * INDIM,
                          W1, w1a, w1b, H1D * INDIM,
                          W2, w2a, w2b, H2D * H1D,
                          W3, w3a, w3b, OUTD * H2D,
                          mem1, BATCH * H1D, mem2, BATCH * H2D,
                          mem3, BATCH * OUTD, out, BATCH * OUTD);

    // ---- 50 timesteps ----
    for (int t = 0; t < TSTEPS; ++t) {
        const __half* x_t = spkin + (size_t)t * BATCH * INDIM;

        // gemm1; for t>0, 16 extra blocks (by>=64, same wave) run the previous
        // step's layer-3 reduction + LIF3 + output accumulation
        gemm_lif<true><<<dim3(2, (t > 0) ? 72 : 64, 1), 256, SMEM>>>(
            x_t, INDIM, w1a, w1b, INDIM, INDIM / 128,
            b1, mem1, s1, H1D, nullptr,
            part, b3, mem3, out);

        gemm_lif<true><<<dim3(2, H2D / 64, 1), 256, SMEM>>>(
            s1, H1D, w2a, w2b, H1D, H1D / 128,
            b2, mem2, s2, H2D, nullptr,
            nullptr, nullptr, nullptr, nullptr);

        // layer 3: single-shot split-K (per-split K = 128 -> nk = 1)
        gemm_lif<false><<<dim3(2, 1, KSPLIT), 256, SMEM>>>(
            s2, H2D, w3a, w3b, H2D, (H2D / KSPLIT) / 128,
            nullptr, nullptr, nullptr, 0, part,
            nullptr, nullptr, nullptr, nullptr);
    }

    // final step's layer-3 reduction
    k_reduce3<<<(BATCH * OUTD) / 256, 256>>>(part, b3, mem3, out);
}

// round 8
// speedup vs baseline: 4.1084x; 1.1337x over previous
#include <cuda_runtime.h>
#include <cuda_fp16.h>
#include <cstdint>
#include <cstddef>

// ============================================================================
// SNN: 50 timesteps of (GEMM + LIF) x 3 layers, portable sm_103 tensor path:
// mma.sync.m16n8k16 + ldmatrix + cp.async.
// Weights split 2-way into fp16 with scaled residual:
//   w = h + m/256,  h = fp16(w), m = fp16(256*(w-h))
// hi comp in FP32 acc; residual in FP16 acc (validated rel_err = 0).
//
// Layer-1 restructuring: all 50 steps of layer-1 currents are computed in ONE
// big GEMM (M = 50*256 = 12800, perfect SM packing), then the layer-1 LIF
// recurrence is run for all steps by one scan kernel (per-neuron independent).
// Per step only gemm2 (+fused layer-3 reduce of t-1) and gemm3 remain.
// ============================================================================

#define TSTEPS 50
#define BATCH  256
#define INDIM  1536
#define H1D    4096
#define H2D    4096
#define OUTD   64
#define KSPLIT 32
#define N1     (BATCH * H1D)          // 1048576 layer-1 neurons*batch

// ---------------- persistent scratch (device globals) -----------------------
__device__ __align__(128) __half g_spk_in[(size_t)TSTEPS * BATCH * INDIM];
__device__ __align__(128) float  g_cur1[(size_t)TSTEPS * N1];      // 210 MB
__device__ __align__(128) __half g_s1_all[(size_t)TSTEPS * N1];    // 105 MB
__device__ __align__(128) __half g_s2[(size_t)BATCH * H2D];
__device__ __align__(128) float g_mem2[(size_t)BATCH * H2D];
__device__ __align__(128) float g_mem3[(size_t)BATCH * OUTD];
__device__ __align__(128) float g_part[(size_t)KSPLIT * BATCH * OUTD];
__device__ __align__(128) __half g_W1a[(size_t)H1D * INDIM];
__device__ __align__(128) __half g_W1b[(size_t)H1D * INDIM];
__device__ __align__(128) __half g_W2a[(size_t)H2D * H1D];
__device__ __align__(128) __half g_W2b[(size_t)H2D * H1D];
__device__ __align__(128) __half g_W3a[(size_t)OUTD * H2D];
__device__ __align__(128) __half g_W3b[(size_t)OUTD * H2D];

// ------------------------------ asm helpers ---------------------------------
__device__ __forceinline__ uint32_t smem_u32(const void* p) {
    uint32_t a;
    asm("{ .reg .u64 t; cvta.to.shared.u64 t, %1; cvt.u32.u64 %0, t; }"
        : "=r"(a) : "l"(p));
    return a;
}

__device__ __forceinline__ void cp16(uint32_t smem, const void* gmem) {
    asm volatile("cp.async.cg.shared.global [%0], [%1], 16;"
                 :: "r"(smem), "l"(gmem) : "memory");
}
__device__ __forceinline__ void cp_commit() {
    asm volatile("cp.async.commit_group;" ::: "memory");
}
template<int N>
__device__ __forceinline__ void cp_wait() {
    asm volatile("cp.async.wait_group %0;" :: "n"(N) : "memory");
}

__device__ __forceinline__ void ldsm4(uint32_t (&r)[4], uint32_t addr) {
    asm volatile("ldmatrix.sync.aligned.m8n8.x4.shared.b16 {%0,%1,%2,%3}, [%4];"
                 : "=r"(r[0]), "=r"(r[1]), "=r"(r[2]), "=r"(r[3]) : "r"(addr));
}

__device__ __forceinline__ void mma_f32(float (&d)[4], const uint32_t (&a)[4],
                                        uint32_t b0, uint32_t b1) {
    asm volatile(
        "mma.sync.aligned.m16n8k16.row.col.f32.f16.f16.f32 "
        "{%0,%1,%2,%3}, {%4,%5,%6,%7}, {%8,%9}, {%0,%1,%2,%3};"
        : "+f"(d[0]), "+f"(d[1]), "+f"(d[2]), "+f"(d[3])
        : "r"(a[0]), "r"(a[1]), "r"(a[2]), "r"(a[3]), "r"(b0), "r"(b1));
}

__device__ __forceinline__ void mma_f16(uint32_t (&d)[2], const uint32_t (&a)[4],
                                        uint32_t b0, uint32_t b1) {
    asm volatile(
        "mma.sync.aligned.m16n8k16.row.col.f16.f16.f16.f16 "
        "{%0,%1}, {%2,%3,%4,%5}, {%6,%7}, {%0,%1};"
        : "+r"(d[0]), "+r"(d[1])
        : "r"(a[0]), "r"(a[1]), "r"(a[2]), "r"(a[3]), "r"(b0), "r"(b1));
}

// ============================================================================
// GEMM kernel, MODE:
//   0 = LIF epilogue (gemm2): cur+bias -> LIF on memv -> spikes; blocks with
//       blockIdx.y >= 64 instead run the previous step's layer-3 reduce+LIF3.
//   1 = split-K fp32 partial store (gemm3).
//   2 = store current + bias fp32, full stride (upfront batched gemm1).
// CTA: M=128 x N=64, 256 threads, warps 4(m) x 2(n), warp tile 32x32.
// 3-stage cp.async ring; stage = K-chunk 128 as two 64-halves = 64KB.
// ============================================================================
template<int MODE>
__global__ void __launch_bounds__(256, 1) gemm_lif(
    const __half* __restrict__ A, int lda,
    const __half* __restrict__ Wa,
    const __half* __restrict__ Wb,
    int ldw, int nk,
    const float* __restrict__ bias,
    float* __restrict__ memv,
    __half* __restrict__ spk, int ldn,
    float* __restrict__ part,
    const float* __restrict__ r_part,
    const float* __restrict__ r_b3,
    float* __restrict__ r_mem3,
    float* __restrict__ r_out)
{
    constexpr int S = 3;
    constexpr int AHALF  = 128 * 128;            // 16KB: 128 rows x 64 f16
    constexpr int ABYTES = 2 * AHALF;            // 32KB
    constexpr int BHALF  = 64 * 128;             // 8KB
    constexpr int BCOMP  = 2 * BHALF;            // 16KB per weight component
    constexpr int STAGE  = ABYTES + 2 * BCOMP;   // 64KB

    const int tid = threadIdx.x;

    // ---- fused reduce blocks (previous step's layer-3 epilogue) -------------
    if (MODE == 0 && blockIdx.y >= 64) {
        const int rblk = ((int)blockIdx.y - 64) * 2 + (int)blockIdx.x;  // 0..15
        const int base = rblk * 1024;
        #pragma unroll
        for (int j = 0; j < 4; ++j) {
            const int idx = base + j * 256 + tid;
            const int n = idx & (OUTD - 1);
            float s = r_b3[n];
            #pragma unroll
            for (int zz = 0; zz < KSPLIT; ++zz)
                s += r_part[(size_t)zz * BATCH * OUTD + idx];
            const float mo = r_mem3[idx];
            const float mn = 0.9f * mo + s - ((mo > 1.0f) ? 1.0f : 0.0f);
            r_mem3[idx] = mn;
            r_out[idx] += ((mn > 1.0f) ? 1.0f : 0.0f);
        }
        return;
    }

    extern __shared__ char smem[];
    const uint32_t sbase = smem_u32(smem);

    const int lane = tid & 31;
    const int wid  = tid >> 5;
    const int m0   = blockIdx.x * 128;
    const int n0   = blockIdx.y * 64;
    const int z    = blockIdx.z;
    const int kbase = (MODE == 1) ? z * nk * 128 : 0;

    const int warp_m = (wid >> 1) * 32;  // 0,32,64,96
    const int warp_n = (wid & 1) * 32;   // 0,32

    // ---- stage loader: K-chunk 128 as two 64-halves --------------------------
    auto load_stage = [&](int L) {
        if (L >= nk) return;
        const uint32_t st = sbase + (uint32_t)(L % S) * STAGE;
        const int k0 = kbase + L * 128;
        #pragma unroll
        for (int h = 0; h < 2; ++h) {
            const int kh = k0 + h * 64;
            #pragma unroll
            for (int i = 0; i < 4; ++i) {
                const int idx  = tid + i * 256;
                const int row  = idx >> 3;
                const int slot = idx & 7;
                const char* g = (const char*)(A + (size_t)(m0 + row) * lda + kh) + slot * 16;
                cp16(st + (uint32_t)h * AHALF + (uint32_t)row * 128u
                        + (uint32_t)((slot ^ (row & 7)) << 4), g);
            }
            #pragma unroll
            for (int c = 0; c < 2; ++c) {
                const __half* W = (c == 0) ? Wa : Wb;
                const uint32_t bb = st + ABYTES + (uint32_t)c * BCOMP + (uint32_t)h * BHALF;
                #pragma unroll
                for (int i = 0; i < 2; ++i) {
                    const int idx  = tid + i * 256;
                    const int row  = idx >> 3;
                    const int slot = idx & 7;
                    const char* g = (const char*)(W + (size_t)(n0 + row) * ldw + kh) + slot * 16;
                    cp16(bb + (uint32_t)row * 128u
                            + (uint32_t)((slot ^ (row & 7)) << 4), g);
                }
            }
        }
    };

    #pragma unroll
    for (int L = 0; L < S - 1; ++L) { load_stage(L); cp_commit(); }

    float    acc [2][4][4];
    uint32_t accr[2][4][2];
    #pragma unroll
    for (int mt = 0; mt < 2; ++mt)
        #pragma unroll
        for (int nt = 0; nt < 4; ++nt) {
            #pragma unroll
            for (int e = 0; e < 4; ++e) acc[mt][nt][e] = 0.0f;
            accr[mt][nt][0] = 0u; accr[mt][nt][1] = 0u;
        }

    const int a_row = (lane & 7) | (((lane >> 3) & 1) << 3);
    const int a_sel = lane >> 4;
    const int b_row = (lane & 7) | (((lane >> 4) & 1) << 3);
    const int b_sel = (lane >> 3) & 1;

    for (int it = 0; it < nk; ++it) {
        cp_wait<S - 2>();
        __syncthreads();
        load_stage(it + S - 1);
        cp_commit();

        const uint32_t st = sbase + (uint32_t)(it % S) * STAGE;

        #pragma unroll
        for (int h = 0; h < 2; ++h) {
            const uint32_t ah = st + (uint32_t)h * AHALF;

            uint32_t afr[2][4][4];
            #pragma unroll
            for (int mt = 0; mt < 2; ++mt) {
                #pragma unroll
                for (int kk = 0; kk < 4; ++kk) {
                    const int row  = warp_m + mt * 16 + a_row;
                    const int slot = kk * 2 + a_sel;
                    ldsm4(afr[mt][kk],
                          ah + (uint32_t)row * 128u + (uint32_t)((slot ^ (row & 7)) << 4));
                }
            }

            {   // hi component (f32 acc)
                const uint32_t bb = st + ABYTES + (uint32_t)h * BHALF;
                uint32_t bfr[4][2][4];
                #pragma unroll
                for (int kk = 0; kk < 4; ++kk) {
                    #pragma unroll
                    for (int jn = 0; jn < 2; ++jn) {
                        const int row  = warp_n + jn * 16 + b_row;
                        const int slot = kk * 2 + b_sel;
                        ldsm4(bfr[kk][jn],
                              bb + (uint32_t)row * 128u + (uint32_t)((slot ^ (row & 7)) << 4));
                    }
                }
                #pragma unroll
                for (int kk = 0; kk < 4; ++kk)
                    #pragma unroll
                    for (int mt = 0; mt < 2; ++mt)
                        #pragma unroll
                        for (int nt = 0; nt < 4; ++nt)
                            mma_f32(acc[mt][nt], afr[mt][kk],
                                    bfr[kk][nt >> 1][(nt & 1) * 2],
                                    bfr[kk][nt >> 1][(nt & 1) * 2 + 1]);
            }

            {   // residual component (f16 acc)
                const uint32_t bb = st + ABYTES + BCOMP + (uint32_t)h * BHALF;
                uint32_t bfr[4][2][4];
                #pragma unroll
                for (int kk = 0; kk < 4; ++kk) {
                    #pragma unroll
                    for (int jn = 0; jn < 2; ++jn) {
                        const int row  = warp_n + jn * 16 + b_row;
                        const int slot = kk * 2 + b_sel;
                        ldsm4(bfr[kk][jn],
                              bb + (uint32_t)row * 128u + (uint32_t)((slot ^ (row & 7)) << 4));
                    }
                }
                #pragma unroll
                for (int kk = 0; kk < 4; ++kk)
                    #pragma unroll
                    for (int mt = 0; mt < 2; ++mt)
                        #pragma unroll
                        for (int nt = 0; nt < 4; ++nt)
                            mma_f16(accr[mt][nt], afr[mt][kk],
                                    bfr[kk][nt >> 1][(nt & 1) * 2],
                                    bfr[kk][nt >> 1][(nt & 1) * 2 + 1]);
            }
        }
    }

    // ---- epilogue -------------------------------------------------------------
    constexpr float SC = 1.0f / 256.0f;
    const int col2 = (lane & 3) * 2;
    const int rowg = lane >> 2;
    #pragma unroll
    for (int mt = 0; mt < 2; ++mt) {
        #pragma unroll
        for (int nt = 0; nt < 4; ++nt) {
            const int n = n0 + warp_n + nt * 8 + col2;
            const int mbase = m0 + warp_m + mt * 16 + rowg;
            const float2 r01 = __half22float2(*(const __half2*)&accr[mt][nt][0]);
            const float2 r23 = __half22float2(*(const __half2*)&accr[mt][nt][1]);
            float cur[4];
            cur[0] = acc[mt][nt][0] + SC * r01.x;
            cur[1] = acc[mt][nt][1] + SC * r01.y;
            cur[2] = acc[mt][nt][2] + SC * r23.x;
            cur[3] = acc[mt][nt][3] + SC * r23.y;
            if (MODE == 0) {
                const float2 bv = *(const float2*)(bias + n);
                #pragma unroll
                for (int h = 0; h < 2; ++h) {
                    const int m = mbase + h * 8;
                    const size_t off = (size_t)m * ldn + n;
                    float2 mo = *(float2*)(memv + off);
                    const float c0 = cur[h * 2 + 0] + bv.x;
                    const float c1 = cur[h * 2 + 1] + bv.y;
                    const float mn0 = 0.9f * mo.x + c0 - ((mo.x > 1.0f) ? 1.0f : 0.0f);
                    const float mn1 = 0.9f * mo.y + c1 - ((mo.y > 1.0f) ? 1.0f : 0.0f);
                    float2 mw; mw.x = mn0; mw.y = mn1;
                    *(float2*)(memv + off) = mw;
                    __half2 sv;
                    sv.x = __float2half((mn0 > 1.0f) ? 1.0f : 0.0f);
                    sv.y = __float2half((mn1 > 1.0f) ? 1.0f : 0.0f);
                    *(__half2*)(spk + off) = sv;
                }
            } else if (MODE == 1) {
                float* po = part + (size_t)z * BATCH * OUTD;
                #pragma unroll
                for (int h = 0; h < 2; ++h) {
                    const int m = mbase + h * 8;
                    float2 pv; pv.x = cur[h * 2 + 0]; pv.y = cur[h * 2 + 1];
                    *(float2*)(po + (size_t)m * OUTD + n) = pv;
                }
            } else {
                const float2 bv = *(const float2*)(bias + n);
                #pragma unroll
                for (int h = 0; h < 2; ++h) {
                    const int m = mbase + h * 8;
                    float2 pv;
                    pv.x = cur[h * 2 + 0] + bv.x;
                    pv.y = cur[h * 2 + 1] + bv.y;
                    *(float2*)(part + (size_t)m * ldn + n) = pv;
                }
            }
        }
    }
}

// ============================================================================
// Layer-1 LIF scan over all 50 steps (per-neuron independent recurrence).
// 262144 threads, float4 per thread.
// ============================================================================
__global__ void k_lif1(const float4* __restrict__ cur, __half2* __restrict__ s) {
    const int i = blockIdx.x * blockDim.x + threadIdx.x;   // 262144 exact
    float4 mem; mem.x = 0.0f; mem.y = 0.0f; mem.z = 0.0f; mem.w = 0.0f;
    for (int t = 0; t < TSTEPS; ++t) {
        const float4 c = cur[(size_t)t * (N1 / 4) + i];
        mem.x = 0.9f * mem.x + c.x - ((mem.x > 1.0f) ? 1.0f : 0.0f);
        mem.y = 0.9f * mem.y + c.y - ((mem.y > 1.0f) ? 1.0f : 0.0f);
        mem.z = 0.9f * mem.z + c.z - ((mem.z > 1.0f) ? 1.0f : 0.0f);
        mem.w = 0.9f * mem.w + c.w - ((mem.w > 1.0f) ? 1.0f : 0.0f);
        __half2 lo, hi;
        lo.x = __float2half((mem.x > 1.0f) ? 1.0f : 0.0f);
        lo.y = __float2half((mem.y > 1.0f) ? 1.0f : 0.0f);
        hi.x = __float2half((mem.z > 1.0f) ? 1.0f : 0.0f);
        hi.y = __float2half((mem.w > 1.0f) ? 1.0f : 0.0f);
        s[(size_t)t * (N1 / 2) + 2 * i]     = lo;
        s[(size_t)t * (N1 / 2) + 2 * i + 1] = hi;
    }
}

// ============================================================================
// Prep: spike convert + weight splits + state zeroing (1 launch)
// ============================================================================
__device__ __forceinline__ void split_one(const float* __restrict__ W,
                                          __half* __restrict__ a,
                                          __half* __restrict__ b,
                                          int n, int gid, int st) {
    for (int i = gid; i < n; i += st) {
        const float w = W[i];
        const __half h = __float2half_rn(w);
        const float r = w - __half2float(h);
        a[i] = h;
        b[i] = __float2half_rn(r * 256.0f);
    }
}

__global__ void k_prep(const float* __restrict__ x, __half* __restrict__ xs, int nx,
                       const float* __restrict__ W1, __half* w1a, __half* w1b, int n1,
                       const float* __restrict__ W2, __half* w2a, __half* w2b, int n2,
                       const float* __restrict__ W3, __half* w3a, __half* w3b, int n3,
                       float* __restrict__ z2, int nz2,
                       float* __restrict__ z3, int nz3,
                       float* __restrict__ z4, int nz4) {
    const int gid = blockIdx.x * blockDim.x + threadIdx.x;
    const int st  = gridDim.x * blockDim.x;
    for (int i = gid; i < nx; i += st) xs[i] = __float2half(x[i]);
    split_one(W1, w1a, w1b, n1, gid, st);
    split_one(W2, w2a, w2b, n2, gid, st);
    split_one(W3, w3a, w3b, n3, gid, st);
    for (int i = gid; i < nz2; i += st) z2[i] = 0.0f;
    for (int i = gid; i < nz3; i += st) z3[i] = 0.0f;
    for (int i = gid; i < nz4; i += st) z4[i] = 0.0f;
}

__global__ void k_reduce3(const float* __restrict__ part,
                          const float* __restrict__ b3,
                          float* __restrict__ mem3,
                          float* __restrict__ out) {
    const int idx = blockIdx.x * blockDim.x + threadIdx.x;   // 16384 exact
    const int n = idx & (OUTD - 1);
    float s = b3[n];
    #pragma unroll
    for (int zz = 0; zz < KSPLIT; ++zz)
        s += part[(size_t)zz * BATCH * OUTD + idx];
    const float mo = mem3[idx];
    const float mn = 0.9f * mo + s - ((mo > 1.0f) ? 1.0f : 0.0f);
    mem3[idx] = mn;
    out[idx] += ((mn > 1.0f) ? 1.0f : 0.0f);
}

// ============================================================================
// Host launcher
// ============================================================================
extern "C" void kernel_launch(void* const* d_in, const int* in_sizes, int n_in,
                              void* d_out, int out_size) {
    (void)in_sizes; (void)n_in; (void)out_size;

    const float* spike_seq = (const float*)d_in[0];
    const float* W1 = (const float*)d_in[1];
    const float* b1 = (const float*)d_in[2];
    const float* W2 = (const float*)d_in[3];
    const float* b2 = (const float*)d_in[4];
    const float* W3 = (const float*)d_in[5];
    const float* b3 = (const float*)d_in[6];
    float* out = (float*)d_out;

    void *p_spk, *p_cur1, *p_s1a, *p_s2, *p_m2, *p_m3, *p_part;
    void *p_w1a, *p_w1b, *p_w2a, *p_w2b, *p_w3a, *p_w3b;
    cudaGetSymbolAddress(&p_spk, g_spk_in);
    cudaGetSymbolAddress(&p_cur1, g_cur1);
    cudaGetSymbolAddress(&p_s1a, g_s1_all);
    cudaGetSymbolAddress(&p_s2, g_s2);
    cudaGetSymbolAddress(&p_m2, g_mem2);
    cudaGetSymbolAddress(&p_m3, g_mem3);
    cudaGetSymbolAddress(&p_part, g_part);
    cudaGetSymbolAddress(&p_w1a, g_W1a); cudaGetSymbolAddress(&p_w1b, g_W1b);
    cudaGetSymbolAddress(&p_w2a, g_W2a); cudaGetSymbolAddress(&p_w2b, g_W2b);
    cudaGetSymbolAddress(&p_w3a, g_W3a); cudaGetSymbolAddress(&p_w3b, g_W3b);

    __half* spkin = (__half*)p_spk;
    float*  cur1  = (float*)p_cur1;
    __half* s1all = (__half*)p_s1a;
    __half* s2    = (__half*)p_s2;
    float* mem2 = (float*)p_m2; float* mem3 = (float*)p_m3;
    float* part = (float*)p_part;
    __half *w1a = (__half*)p_w1a, *w1b = (__half*)p_w1b;
    __half *w2a = (__half*)p_w2a, *w2b = (__half*)p_w2b;
    __half *w3a = (__half*)p_w3a, *w3b = (__half*)p_w3b;

    constexpr int SMEM = 3 * (2 * 128 * 128 + 2 * 2 * 64 * 128);   // 196608
    static int configured = -1;
    if (configured < 0) {
        cudaFuncSetAttribute(gemm_lif<0>,
                             cudaFuncAttributeMaxDynamicSharedMemorySize, SMEM);
        cudaFuncSetAttribute(gemm_lif<1>,
                             cudaFuncAttributeMaxDynamicSharedMemorySize, SMEM);
        cudaFuncSetAttribute(gemm_lif<2>,
                             cudaFuncAttributeMaxDynamicSharedMemorySize, SMEM);
        configured = 1;
    }

    // ---- prep (1 launch) ----
    k_prep<<<1184, 256>>>(spike_seq, spkin, TSTEPS * BATCH * INDIM,
                          W1, w1a, w1b, H1D * INDIM,
                          W2, w2a, w2b, H2D * H1D,
                          W3, w3a, w3b, OUTD * H2D,
                          mem2, BATCH * H2D,
                          mem3, BATCH * OUTD, out, BATCH * OUTD);

    // ---- upfront batched gemm1: all 50 steps, M = 12800 ----
    gemm_lif<2><<<dim3(TSTEPS * BATCH / 128, H1D / 64, 1), 256, SMEM>>>(
        spkin, INDIM, w1a, w1b, INDIM, INDIM / 128,
        b1, nullptr, nullptr, H1D, cur1,
        nullptr, nullptr, nullptr, nullptr);

    // ---- layer-1 LIF scan: all 50 steps ----
    k_lif1<<<N1 / 4 / 256, 256>>>((const float4*)cur1, (__half2*)s1all);

    // ---- 50 timesteps: gemm2 (+fused reduce of t-1) then gemm3 ----
    for (int t = 0; t < TSTEPS; ++t) {
        const __half* s1_t = s1all + (size_t)t * N1;

        gemm_lif<0><<<dim3(2, (t > 0) ? 72 : 64, 1), 256, SMEM>>>(
            s1_t, H1D, w2a, w2b, H1D, H1D / 128,
            b2, mem2, s2, H2D, nullptr,
            part, b3, mem3, out);

        gemm_lif<1><<<dim3(2, 1, KSPLIT), 256, SMEM>>>(
            s2, H2D, w3a, w3b, H2D, (H2D / KSPLIT) / 128,
            nullptr, nullptr, nullptr, 0, part,
            nullptr, nullptr, nullptr, nullptr);
    }

    // final step's layer-3 reduction
    k_reduce3<<<(BATCH * OUTD) / 256, 256>>>(part, b3, mem3, out);
}

// round 9
// speedup vs baseline: 5.0554x; 1.2305x over previous
#include <cuda_runtime.h>
#include <cuda_fp16.h>
#include <cstdint>
#include <cstddef>

// ============================================================================
// SNN, fully batched formulation. Key fact: the only sequential dependency in
// the network is the per-neuron LIF recurrence (elementwise). All GEMMs can be
// batched over the 50 timesteps:
//   gemm1_big: cur1[t,b,:] = x[t,b,:] @ W1^T + b1      (M = 50*256 = 12800)
//   LIF1 scan (per-neuron over t)        -> s1_all
//   gemm2_big: cur2 = s1_all @ W2^T + b2               (M = 12800)
//   LIF2 scan                            -> s2_all
//   gemm3_big: cur3 = s2_all @ W3^T + b3               (M = 12800, N = 64)
//   LIF3 scan + spike-count accumulate   -> out
// 7 kernel launches total.
//
// Tensor path (plain sm_103): mma.sync.m16n8k16 + ldmatrix + cp.async.
// Weights split 2-way into fp16 with scaled residual:
//   w = h + m/256,  h = fp16(w), m = fp16(256*(w-h))
// hi comp in FP32 acc; residual in FP16 acc (validated rel_err = 0).
// ============================================================================

#define TSTEPS 50
#define BATCH  256
#define INDIM  1536
#define H1D    4096
#define H2D    4096
#define OUTD   64
#define MALL   (TSTEPS * BATCH)       // 12800
#define N1     (BATCH * H1D)          // per-step layer-1/2 elements (1048576)

// ---------------- persistent scratch (device globals) -----------------------
__device__ __align__(128) __half g_spk_in[(size_t)MALL * INDIM];
__device__ __align__(128) float  g_cur[(size_t)MALL * H1D];       // 210MB, reused for cur1 then cur2
__device__ __align__(128) __half g_s1_all[(size_t)MALL * H1D];    // 105MB
__device__ __align__(128) __half g_s2_all[(size_t)MALL * H2D];    // 105MB
__device__ __align__(128) float  g_cur3[(size_t)MALL * OUTD];     // 3.3MB
__device__ __align__(128) __half g_W1a[(size_t)H1D * INDIM];
__device__ __align__(128) __half g_W1b[(size_t)H1D * INDIM];
__device__ __align__(128) __half g_W2a[(size_t)H2D * H1D];
__device__ __align__(128) __half g_W2b[(size_t)H2D * H1D];
__device__ __align__(128) __half g_W3a[(size_t)OUTD * H2D];
__device__ __align__(128) __half g_W3b[(size_t)OUTD * H2D];

// ------------------------------ asm helpers ---------------------------------
__device__ __forceinline__ uint32_t smem_u32(const void* p) {
    uint32_t a;
    asm("{ .reg .u64 t; cvta.to.shared.u64 t, %1; cvt.u32.u64 %0, t; }"
        : "=r"(a) : "l"(p));
    return a;
}

__device__ __forceinline__ void cp16(uint32_t smem, const void* gmem) {
    asm volatile("cp.async.cg.shared.global [%0], [%1], 16;"
                 :: "r"(smem), "l"(gmem) : "memory");
}
__device__ __forceinline__ void cp_commit() {
    asm volatile("cp.async.commit_group;" ::: "memory");
}
template<int N>
__device__ __forceinline__ void cp_wait() {
    asm volatile("cp.async.wait_group %0;" :: "n"(N) : "memory");
}

__device__ __forceinline__ void ldsm4(uint32_t (&r)[4], uint32_t addr) {
    asm volatile("ldmatrix.sync.aligned.m8n8.x4.shared.b16 {%0,%1,%2,%3}, [%4];"
                 : "=r"(r[0]), "=r"(r[1]), "=r"(r[2]), "=r"(r[3]) : "r"(addr));
}

__device__ __forceinline__ void mma_f32(float (&d)[4], const uint32_t (&a)[4],
                                        uint32_t b0, uint32_t b1) {
    asm volatile(
        "mma.sync.aligned.m16n8k16.row.col.f32.f16.f16.f32 "
        "{%0,%1,%2,%3}, {%4,%5,%6,%7}, {%8,%9}, {%0,%1,%2,%3};"
        : "+f"(d[0]), "+f"(d[1]), "+f"(d[2]), "+f"(d[3])
        : "r"(a[0]), "r"(a[1]), "r"(a[2]), "r"(a[3]), "r"(b0), "r"(b1));
}

__device__ __forceinline__ void mma_f16(uint32_t (&d)[2], const uint32_t (&a)[4],
                                        uint32_t b0, uint32_t b1) {
    asm volatile(
        "mma.sync.aligned.m16n8k16.row.col.f16.f16.f16.f16 "
        "{%0,%1}, {%2,%3,%4,%5}, {%6,%7}, {%0,%1};"
        : "+r"(d[0]), "+r"(d[1])
        : "r"(a[0]), "r"(a[1]), "r"(a[2]), "r"(a[3]), "r"(b0), "r"(b1));
}

// ============================================================================
// Batched GEMM: D[m,n] = sum_k A[m0+m,k] * (Wa + Wb/256)[n0+n,k] + bias[n]
// stored fp32 to out[m*ldn + n].
// CTA: M=128 x N=64, 256 threads, warps 4(m) x 2(n), warp tile 32x32.
// 3-stage cp.async ring; stage = K-chunk 128 as two 64-halves = 64KB.
// ============================================================================
__global__ void __launch_bounds__(256, 1) gemm_big(
    const __half* __restrict__ A, int lda,
    const __half* __restrict__ Wa,
    const __half* __restrict__ Wb,
    int ldw, int nk,
    const float* __restrict__ bias,
    float* __restrict__ outp, int ldn)
{
    constexpr int S = 3;
    constexpr int AHALF  = 128 * 128;            // 16KB: 128 rows x 64 f16
    constexpr int ABYTES = 2 * AHALF;            // 32KB
    constexpr int BHALF  = 64 * 128;             // 8KB
    constexpr int BCOMP  = 2 * BHALF;            // 16KB per weight component
    constexpr int STAGE  = ABYTES + 2 * BCOMP;   // 64KB

    extern __shared__ char smem[];
    const uint32_t sbase = smem_u32(smem);

    const int tid  = threadIdx.x;
    const int lane = tid & 31;
    const int wid  = tid >> 5;
    const int m0   = blockIdx.x * 128;
    const int n0   = blockIdx.y * 64;

    const int warp_m = (wid >> 1) * 32;  // 0,32,64,96
    const int warp_n = (wid & 1) * 32;   // 0,32

    auto load_stage = [&](int L) {
        if (L >= nk) return;
        const uint32_t st = sbase + (uint32_t)(L % S) * STAGE;
        const int k0 = L * 128;
        #pragma unroll
        for (int h = 0; h < 2; ++h) {
            const int kh = k0 + h * 64;
            #pragma unroll
            for (int i = 0; i < 4; ++i) {
                const int idx  = tid + i * 256;
                const int row  = idx >> 3;
                const int slot = idx & 7;
                const char* g = (const char*)(A + (size_t)(m0 + row) * lda + kh) + slot * 16;
                cp16(st + (uint32_t)h * AHALF + (uint32_t)row * 128u
                        + (uint32_t)((slot ^ (row & 7)) << 4), g);
            }
            #pragma unroll
            for (int c = 0; c < 2; ++c) {
                const __half* W = (c == 0) ? Wa : Wb;
                const uint32_t bb = st + ABYTES + (uint32_t)c * BCOMP + (uint32_t)h * BHALF;
                #pragma unroll
                for (int i = 0; i < 2; ++i) {
                    const int idx  = tid + i * 256;
                    const int row  = idx >> 3;
                    const int slot = idx & 7;
                    const char* g = (const char*)(W + (size_t)(n0 + row) * ldw + kh) + slot * 16;
                    cp16(bb + (uint32_t)row * 128u
                            + (uint32_t)((slot ^ (row & 7)) << 4), g);
                }
            }
        }
    };

    #pragma unroll
    for (int L = 0; L < S - 1; ++L) { load_stage(L); cp_commit(); }

    float    acc [2][4][4];
    uint32_t accr[2][4][2];
    #pragma unroll
    for (int mt = 0; mt < 2; ++mt)
        #pragma unroll
        for (int nt = 0; nt < 4; ++nt) {
            #pragma unroll
            for (int e = 0; e < 4; ++e) acc[mt][nt][e] = 0.0f;
            accr[mt][nt][0] = 0u; accr[mt][nt][1] = 0u;
        }

    const int a_row = (lane & 7) | (((lane >> 3) & 1) << 3);
    const int a_sel = lane >> 4;
    const int b_row = (lane & 7) | (((lane >> 4) & 1) << 3);
    const int b_sel = (lane >> 3) & 1;

    for (int it = 0; it < nk; ++it) {
        cp_wait<S - 2>();
        __syncthreads();
        load_stage(it + S - 1);
        cp_commit();

        const uint32_t st = sbase + (uint32_t)(it % S) * STAGE;

        #pragma unroll
        for (int h = 0; h < 2; ++h) {
            const uint32_t ah = st + (uint32_t)h * AHALF;

            uint32_t afr[2][4][4];
            #pragma unroll
            for (int mt = 0; mt < 2; ++mt) {
                #pragma unroll
                for (int kk = 0; kk < 4; ++kk) {
                    const int row  = warp_m + mt * 16 + a_row;
                    const int slot = kk * 2 + a_sel;
                    ldsm4(afr[mt][kk],
                          ah + (uint32_t)row * 128u + (uint32_t)((slot ^ (row & 7)) << 4));
                }
            }

            {   // hi component (f32 acc)
                const uint32_t bb = st + ABYTES + (uint32_t)h * BHALF;
                uint32_t bfr[4][2][4];
                #pragma unroll
                for (int kk = 0; kk < 4; ++kk) {
                    #pragma unroll
                    for (int jn = 0; jn < 2; ++jn) {
                        const int row  = warp_n + jn * 16 + b_row;
                        const int slot = kk * 2 + b_sel;
                        ldsm4(bfr[kk][jn],
                              bb + (uint32_t)row * 128u + (uint32_t)((slot ^ (row & 7)) << 4));
                    }
                }
                #pragma unroll
                for (int kk = 0; kk < 4; ++kk)
                    #pragma unroll
                    for (int mt = 0; mt < 2; ++mt)
                        #pragma unroll
                        for (int nt = 0; nt < 4; ++nt)
                            mma_f32(acc[mt][nt], afr[mt][kk],
                                    bfr[kk][nt >> 1][(nt & 1) * 2],
                                    bfr[kk][nt >> 1][(nt & 1) * 2 + 1]);
            }

            {   // residual component (f16 acc)
                const uint32_t bb = st + ABYTES + BCOMP + (uint32_t)h * BHALF;
                uint32_t bfr[4][2][4];
                #pragma unroll
                for (int kk = 0; kk < 4; ++kk) {
                    #pragma unroll
                    for (int jn = 0; jn < 2; ++jn) {
                        const int row  = warp_n + jn * 16 + b_row;
                        const int slot = kk * 2 + b_sel;
                        ldsm4(bfr[kk][jn],
                              bb + (uint32_t)row * 128u + (uint32_t)((slot ^ (row & 7)) << 4));
                    }
                }
                #pragma unroll
                for (int kk = 0; kk < 4; ++kk)
                    #pragma unroll
                    for (int mt = 0; mt < 2; ++mt)
                        #pragma unroll
                        for (int nt = 0; nt < 4; ++nt)
                            mma_f16(accr[mt][nt], afr[mt][kk],
                                    bfr[kk][nt >> 1][(nt & 1) * 2],
                                    bfr[kk][nt >> 1][(nt & 1) * 2 + 1]);
            }
        }
    }

    // ---- epilogue: combine, add bias, store fp32 ------------------------------
    constexpr float SC = 1.0f / 256.0f;
    const int col2 = (lane & 3) * 2;
    const int rowg = lane >> 2;
    #pragma unroll
    for (int mt = 0; mt < 2; ++mt) {
        #pragma unroll
        for (int nt = 0; nt < 4; ++nt) {
            const int n = n0 + warp_n + nt * 8 + col2;
            const int mbase = m0 + warp_m + mt * 16 + rowg;
            const float2 r01 = __half22float2(*(const __half2*)&accr[mt][nt][0]);
            const float2 r23 = __half22float2(*(const __half2*)&accr[mt][nt][1]);
            const float2 bv = *(const float2*)(bias + n);
            float2 v0, v1;
            v0.x = acc[mt][nt][0] + SC * r01.x + bv.x;
            v0.y = acc[mt][nt][1] + SC * r01.y + bv.y;
            v1.x = acc[mt][nt][2] + SC * r23.x + bv.x;
            v1.y = acc[mt][nt][3] + SC * r23.y + bv.y;
            *(float2*)(outp + (size_t)mbase * ldn + n)       = v0;
            *(float2*)(outp + (size_t)(mbase + 8) * ldn + n) = v1;
        }
    }
}

// ============================================================================
// LIF scan over all 50 steps for 4096-wide layers (per-neuron independent).
// 262144 threads, float4 per thread; spikes out as __half pairs.
// ============================================================================
__global__ void k_lif_scan(const float4* __restrict__ cur, __half2* __restrict__ s) {
    const int i = blockIdx.x * blockDim.x + threadIdx.x;   // N1/4 threads exact
    float4 mem; mem.x = 0.0f; mem.y = 0.0f; mem.z = 0.0f; mem.w = 0.0f;
    for (int t = 0; t < TSTEPS; ++t) {
        const float4 c = cur[(size_t)t * (N1 / 4) + i];
        mem.x = 0.9f * mem.x + c.x - ((mem.x > 1.0f) ? 1.0f : 0.0f);
        mem.y = 0.9f * mem.y + c.y - ((mem.y > 1.0f) ? 1.0f : 0.0f);
        mem.z = 0.9f * mem.z + c.z - ((mem.z > 1.0f) ? 1.0f : 0.0f);
        mem.w = 0.9f * mem.w + c.w - ((mem.w > 1.0f) ? 1.0f : 0.0f);
        __half2 lo, hi;
        lo.x = __float2half((mem.x > 1.0f) ? 1.0f : 0.0f);
        lo.y = __float2half((mem.y > 1.0f) ? 1.0f : 0.0f);
        hi.x = __float2half((mem.z > 1.0f) ? 1.0f : 0.0f);
        hi.y = __float2half((mem.w > 1.0f) ? 1.0f : 0.0f);
        s[(size_t)t * (N1 / 2) + 2 * i]     = lo;
        s[(size_t)t * (N1 / 2) + 2 * i + 1] = hi;
    }
}

// ============================================================================
// LIF3 scan + output spike-count accumulate (16384 independent scans).
// ============================================================================
__global__ void k_lif3(const float* __restrict__ cur3, float* __restrict__ out) {
    const int idx = blockIdx.x * blockDim.x + threadIdx.x;   // 16384 exact
    float mem = 0.0f, s = 0.0f;
    for (int t = 0; t < TSTEPS; ++t) {
        const float c = cur3[(size_t)t * (BATCH * OUTD) + idx];
        mem = 0.9f * mem + c - ((mem > 1.0f) ? 1.0f : 0.0f);
        s += ((mem > 1.0f) ? 1.0f : 0.0f);
    }
    out[idx] = s;
}

// ============================================================================
// Prep: spike convert + weight splits (1 launch)
// ============================================================================
__device__ __forceinline__ void split_one(const float* __restrict__ W,
                                          __half* __restrict__ a,
                                          __half* __restrict__ b,
                                          int n, int gid, int st) {
    for (int i = gid; i < n; i += st) {
        const float w = W[i];
        const __half h = __float2half_rn(w);
        const float r = w - __half2float(h);
        a[i] = h;
        b[i] = __float2half_rn(r * 256.0f);
    }
}

__global__ void k_prep(const float* __restrict__ x, __half* __restrict__ xs, int nx,
                       const float* __restrict__ W1, __half* w1a, __half* w1b, int n1,
                       const float* __restrict__ W2, __half* w2a, __half* w2b, int n2,
                       const float* __restrict__ W3, __half* w3a, __half* w3b, int n3) {
    const int gid = blockIdx.x * blockDim.x + threadIdx.x;
    const int st  = gridDim.x * blockDim.x;
    for (int i = gid; i < nx; i += st) xs[i] = __float2half(x[i]);
    split_one(W1, w1a, w1b, n1, gid, st);
    split_one(W2, w2a, w2b, n2, gid, st);
    split_one(W3, w3a, w3b, n3, gid, st);
}

// ============================================================================
// Host launcher: 7 kernel launches total.
// ============================================================================
extern "C" void kernel_launch(void* const* d_in, const int* in_sizes, int n_in,
                              void* d_out, int out_size) {
    (void)in_sizes; (void)n_in; (void)out_size;

    const float* spike_seq = (const float*)d_in[0];
    const float* W1 = (const float*)d_in[1];
    const float* b1 = (const float*)d_in[2];
    const float* W2 = (const float*)d_in[3];
    const float* b2 = (const float*)d_in[4];
    const float* W3 = (const float*)d_in[5];
    const float* b3 = (const float*)d_in[6];
    float* out = (float*)d_out;

    void *p_spk, *p_cur, *p_s1a, *p_s2a, *p_cur3;
    void *p_w1a, *p_w1b, *p_w2a, *p_w2b, *p_w3a, *p_w3b;
    cudaGetSymbolAddress(&p_spk, g_spk_in);
    cudaGetSymbolAddress(&p_cur, g_cur);
    cudaGetSymbolAddress(&p_s1a, g_s1_all);
    cudaGetSymbolAddress(&p_s2a, g_s2_all);
    cudaGetSymbolAddress(&p_cur3, g_cur3);
    cudaGetSymbolAddress(&p_w1a, g_W1a); cudaGetSymbolAddress(&p_w1b, g_W1b);
    cudaGetSymbolAddress(&p_w2a, g_W2a); cudaGetSymbolAddress(&p_w2b, g_W2b);
    cudaGetSymbolAddress(&p_w3a, g_W3a); cudaGetSymbolAddress(&p_w3b, g_W3b);

    __half* spkin = (__half*)p_spk;
    float*  cur   = (float*)p_cur;
    __half* s1all = (__half*)p_s1a;
    __half* s2all = (__half*)p_s2a;
    float*  cur3  = (float*)p_cur3;
    __half *w1a = (__half*)p_w1a, *w1b = (__half*)p_w1b;
    __half *w2a = (__half*)p_w2a, *w2b = (__half*)p_w2b;
    __half *w3a = (__half*)p_w3a, *w3b = (__half*)p_w3b;

    constexpr int SMEM = 3 * (2 * 128 * 128 + 2 * 2 * 64 * 128);   // 196608
    static int configured = -1;
    if (configured < 0) {
        cudaFuncSetAttribute(gemm_big,
                             cudaFuncAttributeMaxDynamicSharedMemorySize, SMEM);
        configured = 1;
    }

    // 1) prep
    k_prep<<<1184, 256>>>(spike_seq, spkin, MALL * INDIM,
                          W1, w1a, w1b, H1D * INDIM,
                          W2, w2a, w2b, H2D * H1D,
                          W3, w3a, w3b, OUTD * H2D);

    // 2) gemm1_big: cur1 = x @ W1^T + b1   (M=12800, N=4096, K=1536)
    gemm_big<<<dim3(MALL / 128, H1D / 64), 256, SMEM>>>(
        spkin, INDIM, w1a, w1b, INDIM, INDIM / 128, b1, cur, H1D);

    // 3) LIF1 scan -> s1_all
    k_lif_scan<<<N1 / 4 / 256, 256>>>((const float4*)cur, (__half2*)s1all);

    // 4) gemm2_big: cur2 = s1_all @ W2^T + b2   (M=12800, N=4096, K=4096)
    gemm_big<<<dim3(MALL / 128, H2D / 64), 256, SMEM>>>(
        s1all, H1D, w2a, w2b, H1D, H1D / 128, b2, cur, H2D);

    // 5) LIF2 scan -> s2_all
    k_lif_scan<<<N1 / 4 / 256, 256>>>((const float4*)cur, (__half2*)s2all);

    // 6) gemm3_big: cur3 = s2_all @ W3^T + b3   (M=12800, N=64, K=4096)
    gemm_big<<<dim3(MALL / 128, 1), 256, SMEM>>>(
        s2all, H2D, w3a, w3b, H2D, H2D / 128, b3, cur3, OUTD);

    // 7) LIF3 scan + output accumulate
    k_lif3<<<(BATCH * OUTD) / 256, 256>>>(cur3, out);
}